// round 1
// baseline (speedup 1.0000x reference)
#include <cuda_runtime.h>
#include <cuda_bf16.h>
#include <math.h>

#define BSZ 2
#define SEQ 2048
#define DM  2048
#define HQ  16
#define HKV 4
#define HD  128
#define MROWS (BSZ*SEQ)        // 4096
#define KVD (HKV*HD)           // 512

// scratch (module-load allocated; no runtime allocs)
__device__ float g_q [BSZ*SEQ*HQ*HD];   // (b,s,h,d)
__device__ float g_k [BSZ*SEQ*HKV*HD];
__device__ float g_v [BSZ*SEQ*HKV*HD];
__device__ float g_ao[BSZ*SEQ*HQ*HD];

// ---------------- C = A(MxK) @ W(KxN) + bias, row-major, 128x128x8 tiles ----
__global__ __launch_bounds__(256) void sgemm_bias(
    const float* __restrict__ A, const float* __restrict__ W,
    const float* __restrict__ bias, float* __restrict__ C,
    int M, int N, int K)
{
    __shared__ float As[8][128];
    __shared__ float Ws[8][128];
    const int t = threadIdx.x;
    const int mBase = blockIdx.y * 128;
    const int nBase = blockIdx.x * 128;
    const int tx = t & 15, ty = t >> 4;          // 16x16 threads, 8x8 each
    const int arow = t >> 1, ach = (t & 1) * 4;  // A tile loader
    const int wrow = t >> 5, wcol = (t & 31) * 4;// W tile loader

    float acc[8][8];
    #pragma unroll
    for (int i = 0; i < 8; i++)
        #pragma unroll
        for (int j = 0; j < 8; j++) acc[i][j] = 0.f;

    for (int k0 = 0; k0 < K; k0 += 8) {
        float4 a4 = *(const float4*)(A + (size_t)(mBase + arow) * K + k0 + ach);
        As[ach + 0][arow] = a4.x; As[ach + 1][arow] = a4.y;
        As[ach + 2][arow] = a4.z; As[ach + 3][arow] = a4.w;
        float4 w4 = *(const float4*)(W + (size_t)(k0 + wrow) * N + nBase + wcol);
        *(float4*)&Ws[wrow][wcol] = w4;
        __syncthreads();
        #pragma unroll
        for (int k = 0; k < 8; k++) {
            float a[8], b[8];
            #pragma unroll
            for (int i = 0; i < 8; i++) a[i] = As[k][ty * 8 + i];
            #pragma unroll
            for (int j = 0; j < 8; j++) b[j] = Ws[k][tx * 8 + j];
            #pragma unroll
            for (int i = 0; i < 8; i++)
                #pragma unroll
                for (int j = 0; j < 8; j++) acc[i][j] += a[i] * b[j];
        }
        __syncthreads();
    }

    float bb[8];
    #pragma unroll
    for (int j = 0; j < 8; j++)
        bb[j] = bias ? bias[nBase + tx * 8 + j] : 0.f;

    #pragma unroll
    for (int i = 0; i < 8; i++) {
        const size_t row = mBase + ty * 8 + i;
        #pragma unroll
        for (int j = 0; j < 8; j++)
            C[row * N + nBase + tx * 8 + j] = acc[i][j] + bb[j];
    }
}

// ---------------- RoPE in-place on (b,s,nh,128) ----------------------------
__global__ void rope_kernel(float* __restrict__ buf,
                            const float* __restrict__ cosb,
                            const float* __restrict__ sinb,
                            int nh, int total)
{
    int idx = blockIdx.x * blockDim.x + threadIdx.x;
    if (idx >= total) return;
    int pair = idx & 63;
    int h = (idx >> 6) % nh;
    int s = (idx / (64 * nh)) % SEQ;
    int b = idx / (64 * nh * SEQ);
    size_t base = (((size_t)b * SEQ + s) * nh + h) * HD;
    float xr = buf[base + 2 * pair];
    float xi = buf[base + 2 * pair + 1];
    float c  = cosb[s * 64 + pair];
    float sn = sinb[s * 64 + pair];
    buf[base + 2 * pair]     = xr * c - xi * sn;
    buf[base + 2 * pair + 1] = xr * sn + xi * c;
}

// ---------------- scores: attn[bh,i,j] = scale * q_i . k_j  (causal skip) ---
__global__ __launch_bounds__(256) void scores_kernel(
    const float* __restrict__ q, const float* __restrict__ k,
    float* __restrict__ attn, float scale)
{
    const int bx = blockIdx.x, by = blockIdx.y;
    if (bx > by) return;                       // whole tile above diagonal
    const int bh = blockIdx.z;
    const int b = bh >> 4, h = bh & 15, hk = h >> 2;

    __shared__ float Qs[16][64];
    __shared__ float Ks[16][64];
    const int t = threadIdx.x;
    const int tx = t & 15, ty = t >> 4;        // 4x4 per thread -> 64x64
    const int lr = t >> 2, lc = (t & 3) * 4;   // 64 rows x 16 cols loader

    const float* qp = q + (size_t)b * SEQ * DM + (size_t)h * HD;   // row stride DM
    const float* kp = k + (size_t)b * SEQ * KVD + (size_t)hk * HD; // row stride KVD

    float acc[4][4];
    #pragma unroll
    for (int i = 0; i < 4; i++)
        #pragma unroll
        for (int j = 0; j < 4; j++) acc[i][j] = 0.f;

    for (int d0 = 0; d0 < HD; d0 += 16) {
        float4 q4 = *(const float4*)(qp + (size_t)(by * 64 + lr) * DM + d0 + lc);
        Qs[lc + 0][lr] = q4.x; Qs[lc + 1][lr] = q4.y;
        Qs[lc + 2][lr] = q4.z; Qs[lc + 3][lr] = q4.w;
        float4 k4 = *(const float4*)(kp + (size_t)(bx * 64 + lr) * KVD + d0 + lc);
        Ks[lc + 0][lr] = k4.x; Ks[lc + 1][lr] = k4.y;
        Ks[lc + 2][lr] = k4.z; Ks[lc + 3][lr] = k4.w;
        __syncthreads();
        #pragma unroll
        for (int d = 0; d < 16; d++) {
            float a[4], bb[4];
            #pragma unroll
            for (int r = 0; r < 4; r++) a[r]  = Qs[d][ty * 4 + r];
            #pragma unroll
            for (int c = 0; c < 4; c++) bb[c] = Ks[d][tx * 4 + c];
            #pragma unroll
            for (int r = 0; r < 4; r++)
                #pragma unroll
                for (int c = 0; c < 4; c++) acc[r][c] += a[r] * bb[c];
        }
        __syncthreads();
    }

    float* op = attn + ((size_t)bh * SEQ + by * 64) * SEQ + bx * 64;
    #pragma unroll
    for (int r = 0; r < 4; r++)
        #pragma unroll
        for (int c = 0; c < 4; c++)
            op[(size_t)(ty * 4 + r) * SEQ + tx * 4 + c] = acc[r][c] * scale;
}

// ---------------- row softmax, causal zeros above diagonal ------------------
__global__ __launch_bounds__(256) void softmax_kernel(float* __restrict__ attn)
{
    const int row = blockIdx.x;            // b*HQ*SEQ rows
    const int i = row & (SEQ - 1);
    const int len = i + 1;
    float* p = attn + (size_t)row * SEQ;
    const int t = threadIdx.x;
    __shared__ float red[256];

    float vals[8];
    float m = -INFINITY;
    #pragma unroll
    for (int c = 0; c < 8; c++) {
        int j = c * 256 + t;
        if (j < len) { vals[c] = p[j]; m = fmaxf(m, vals[c]); }
    }
    red[t] = m; __syncthreads();
    for (int s = 128; s > 0; s >>= 1) {
        if (t < s) red[t] = fmaxf(red[t], red[t + s]);
        __syncthreads();
    }
    m = red[0]; __syncthreads();

    float l = 0.f;
    #pragma unroll
    for (int c = 0; c < 8; c++) {
        int j = c * 256 + t;
        if (j < len) { float e = __expf(vals[c] - m); vals[c] = e; l += e; }
    }
    red[t] = l; __syncthreads();
    for (int s = 128; s > 0; s >>= 1) {
        if (t < s) red[t] += red[t + s];
        __syncthreads();
    }
    const float inv = 1.0f / red[0];

    #pragma unroll
    for (int c = 0; c < 8; c++) {
        int j = c * 256 + t;
        if (j < len) p[j] = vals[c] * inv;
    }
    for (int j = len + t; j < SEQ; j += 256) p[j] = 0.f;   // required: d_out poisoned
}

// ---------------- out_h = attn @ v  (causal K-loop truncation) --------------
__global__ __launch_bounds__(256) void attnv_kernel(
    const float* __restrict__ attn, const float* __restrict__ v,
    float* __restrict__ ao)
{
    const int bh = blockIdx.y;
    const int b = bh >> 4, h = bh & 15, hk = h >> 2;
    const int row0 = blockIdx.x * 64;

    __shared__ float Ps[16][64];
    __shared__ float Vs[16][128];
    const int t = threadIdx.x;
    const int tx = t & 15, ty = t >> 4;        // rows: ty*4 (64) ; cols: tx*8 (128)
    const int lr = t >> 2, lc = (t & 3) * 4;

    const float* pp = attn + ((size_t)bh * SEQ + row0) * SEQ;
    const float* vp = v + (size_t)b * SEQ * KVD + (size_t)hk * HD;

    float acc[4][8];
    #pragma unroll
    for (int r = 0; r < 4; r++)
        #pragma unroll
        for (int c = 0; c < 8; c++) acc[r][c] = 0.f;

    const int jlim = row0 + 64;                // attn is 0 for j > i
    for (int j0 = 0; j0 < jlim; j0 += 16) {
        float4 p4 = *(const float4*)(pp + (size_t)lr * SEQ + j0 + lc);
        Ps[lc + 0][lr] = p4.x; Ps[lc + 1][lr] = p4.y;
        Ps[lc + 2][lr] = p4.z; Ps[lc + 3][lr] = p4.w;
        #pragma unroll
        for (int q2 = 0; q2 < 2; q2++) {
            int idx = t + q2 * 256;
            int vr = idx >> 5, vc = (idx & 31) * 4;
            *(float4*)&Vs[vr][vc] =
                *(const float4*)(vp + (size_t)(j0 + vr) * KVD + vc);
        }
        __syncthreads();
        #pragma unroll
        for (int d = 0; d < 16; d++) {
            float a[4], bb[8];
            #pragma unroll
            for (int r = 0; r < 4; r++) a[r]  = Ps[d][ty * 4 + r];
            #pragma unroll
            for (int c = 0; c < 8; c++) bb[c] = Vs[d][tx * 8 + c];
            #pragma unroll
            for (int r = 0; r < 4; r++)
                #pragma unroll
                for (int c = 0; c < 8; c++) acc[r][c] += a[r] * bb[c];
        }
        __syncthreads();
    }

    #pragma unroll
    for (int r = 0; r < 4; r++) {
        const size_t orow = (size_t)b * SEQ + row0 + ty * 4 + r;
        #pragma unroll
        for (int c = 0; c < 8; c++)
            ao[orow * DM + h * HD + tx * 8 + c] = acc[r][c];
    }
}

extern "C" void kernel_launch(void* const* d_in, const int* in_sizes, int n_in,
                              void* d_out, int out_size)
{
    const float* x  = (const float*)d_in[0];
    const float* fc = (const float*)d_in[1];
    const float* fs = (const float*)d_in[2];
    const float* wq = (const float*)d_in[3];
    const float* bq = (const float*)d_in[4];
    const float* wk = (const float*)d_in[5];
    const float* bk = (const float*)d_in[6];
    const float* wv = (const float*)d_in[7];
    const float* bv = (const float*)d_in[8];
    const float* wo = (const float*)d_in[9];

    float* outp = (float*)d_out;
    float* attn = outp + (size_t)BSZ * SEQ * DM;   // (b,h,s,t)

    float *qb, *kb, *vb, *aob;
    cudaGetSymbolAddress((void**)&qb,  g_q);
    cudaGetSymbolAddress((void**)&kb,  g_k);
    cudaGetSymbolAddress((void**)&vb,  g_v);
    cudaGetSymbolAddress((void**)&aob, g_ao);

    const float scale = 1.0f / sqrtf((float)DM);

    // projections
    sgemm_bias<<<dim3(DM / 128, MROWS / 128), 256>>>(x, wq, bq, qb, MROWS, DM, DM);
    sgemm_bias<<<dim3(KVD / 128, MROWS / 128), 256>>>(x, wk, bk, kb, MROWS, KVD, DM);
    sgemm_bias<<<dim3(KVD / 128, MROWS / 128), 256>>>(x, wv, bv, vb, MROWS, KVD, DM);

    // rope
    {
        int totq = BSZ * SEQ * HQ * 64;
        rope_kernel<<<totq / 256, 256>>>(qb, fc, fs, HQ, totq);
        int totk = BSZ * SEQ * HKV * 64;
        rope_kernel<<<totk / 256, 256>>>(kb, fc, fs, HKV, totk);
    }

    // attention
    scores_kernel<<<dim3(SEQ / 64, SEQ / 64, BSZ * HQ), 256>>>(qb, kb, attn, scale);
    softmax_kernel<<<BSZ * HQ * SEQ, 256>>>(attn);
    attnv_kernel<<<dim3(SEQ / 64, BSZ * HQ), 256>>>(attn, vb, aob);

    // output projection
    sgemm_bias<<<dim3(DM / 128, MROWS / 128), 256>>>(aob, wo, nullptr, outp, MROWS, DM, DM);
}

// round 2
// speedup vs baseline: 2.0366x; 2.0366x over previous
#include <cuda_runtime.h>
#include <math.h>

#define BSZ 2
#define SEQ 2048
#define DM  2048
#define HQ  16
#define HKV 4
#define HD  128
#define MROWS (BSZ*SEQ)        // 4096
#define KVD (HKV*HD)           // 512

// scratch (module-load allocated; no runtime allocs)
__device__ float g_q [(size_t)BSZ*SEQ*HQ*HD];
__device__ float g_k [(size_t)BSZ*SEQ*HKV*HD];
__device__ float g_v [(size_t)BSZ*SEQ*HKV*HD];
__device__ float g_ao[(size_t)BSZ*SEQ*HQ*HD];

__device__ __forceinline__ unsigned f2tf(float x){
    unsigned u; asm("cvt.rna.tf32.f32 %0, %1;" : "=r"(u) : "f"(x)); return u;
}
__device__ __forceinline__ void mma_tf32(float* d, const unsigned* a, const unsigned* b){
    asm volatile("mma.sync.aligned.m16n8k8.row.col.f32.tf32.tf32.f32 "
        "{%0,%1,%2,%3}, {%4,%5,%6,%7}, {%8,%9}, {%0,%1,%2,%3};"
        : "+f"(d[0]), "+f"(d[1]), "+f"(d[2]), "+f"(d[3])
        : "r"(a[0]), "r"(a[1]), "r"(a[2]), "r"(a[3]), "r"(b[0]), "r"(b[1]));
}

// ============ C[M,N] = A[M,K] @ W[K,N] + bias  (tf32 tensor core) ==========
// block 128x128, kTile 32, 8 warps (2x4), warp tile 64x32
__global__ __launch_bounds__(256) void gemm_tf32(
    const float* __restrict__ A, const float* __restrict__ W,
    const float* __restrict__ bias, float* __restrict__ C,
    int M, int N, int K)
{
    __shared__ unsigned As[128][40];   // [m][k] pad->bank (8r+c)%32 distinct
    __shared__ unsigned Bs[32][136];   // [k][n] pad->bank (8k+n)%32 distinct
    const int t = threadIdx.x, lane = t & 31, w = t >> 5;
    const int wm = w >> 2, wn = w & 3;
    const int gid = lane >> 2, tg = lane & 3;
    const int mBase = blockIdx.y * 128, nBase = blockIdx.x * 128;

    const int ar = t >> 1, ac = (t & 1) * 16;   // A loader: 128 x 32
    const int br = t >> 3, bc = (t & 7) * 16;   // B loader: 32 x 128

    float acc[4][4][4];
    #pragma unroll
    for (int i=0;i<4;i++)
        #pragma unroll
        for (int j=0;j<4;j++)
            #pragma unroll
            for (int v=0;v<4;v++) acc[i][j][v]=0.f;

    const float* Ap = A + (size_t)(mBase + ar) * K + ac;
    const float* Wp = W + (size_t)br * N + nBase + bc;

    float4 pa[4], pb[4];
    #pragma unroll
    for (int i=0;i<4;i++) pa[i] = *(const float4*)(Ap + i*4);
    #pragma unroll
    for (int i=0;i<4;i++) pb[i] = *(const float4*)(Wp + i*4);

    const int niter = K >> 5;
    for (int it = 0; it < niter; ++it) {
        #pragma unroll
        for (int i=0;i<4;i++)
            *(uint4*)&As[ar][ac + i*4] =
                make_uint4(f2tf(pa[i].x),f2tf(pa[i].y),f2tf(pa[i].z),f2tf(pa[i].w));
        #pragma unroll
        for (int i=0;i<4;i++)
            *(uint4*)&Bs[br][bc + i*4] =
                make_uint4(f2tf(pb[i].x),f2tf(pb[i].y),f2tf(pb[i].z),f2tf(pb[i].w));
        __syncthreads();
        if (it + 1 < niter) {
            const float* Ap2 = Ap + (it+1)*32;
            const float* Wp2 = Wp + (size_t)(it+1)*32*N;
            #pragma unroll
            for (int i=0;i<4;i++) pa[i] = *(const float4*)(Ap2 + i*4);
            #pragma unroll
            for (int i=0;i<4;i++) pb[i] = *(const float4*)(Wp2 + i*4);
        }
        #pragma unroll
        for (int ks=0; ks<4; ++ks){
            unsigned af[4][4], bf[4][2];
            #pragma unroll
            for (int mt=0;mt<4;mt++){
                const int r = wm*64 + mt*16 + gid, c = ks*8 + tg;
                af[mt][0]=As[r][c];   af[mt][1]=As[r+8][c];
                af[mt][2]=As[r][c+4]; af[mt][3]=As[r+8][c+4];
            }
            #pragma unroll
            for (int nt=0;nt<4;nt++){
                const int n = wn*32 + nt*8 + gid, kk = ks*8 + tg;
                bf[nt][0]=Bs[kk][n]; bf[nt][1]=Bs[kk+4][n];
            }
            #pragma unroll
            for (int mt=0;mt<4;mt++)
                #pragma unroll
                for (int nt=0;nt<4;nt++)
                    mma_tf32(acc[mt][nt], af[mt], bf[nt]);
        }
        __syncthreads();
    }

    #pragma unroll
    for (int mt=0;mt<4;mt++){
        const int r = mBase + wm*64 + mt*16 + gid;
        #pragma unroll
        for (int nt=0;nt<4;nt++){
            const int cn = nBase + wn*32 + nt*8 + tg*2;
            float b0 = bias ? bias[cn]   : 0.f;
            float b1 = bias ? bias[cn+1] : 0.f;
            *(float2*)(C + (size_t)r*N + cn) =
                make_float2(acc[mt][nt][0]+b0, acc[mt][nt][1]+b1);
            *(float2*)(C + (size_t)(r+8)*N + cn) =
                make_float2(acc[mt][nt][2]+b0, acc[mt][nt][3]+b1);
        }
    }
}

// ---------------- RoPE in-place on (b,s,nh,128) ----------------------------
__global__ void rope_kernel(float* __restrict__ buf,
                            const float* __restrict__ cosb,
                            const float* __restrict__ sinb,
                            int nh, int total)
{
    int idx = blockIdx.x * blockDim.x + threadIdx.x;
    if (idx >= total) return;
    int pair = idx & 63;
    int h = (idx >> 6) % nh;
    int s = (idx / (64 * nh)) % SEQ;
    int b = idx / (64 * nh * SEQ);
    size_t base = (((size_t)b * SEQ + s) * nh + h) * HD;
    float xr = buf[base + 2 * pair];
    float xi = buf[base + 2 * pair + 1];
    float c  = cosb[s * 64 + pair];
    float sn = sinb[s * 64 + pair];
    buf[base + 2 * pair]     = xr * c - xi * sn;
    buf[base + 2 * pair + 1] = xr * sn + xi * c;
}

// ======= scores[bh,i,j] = scale * q_i.k_j  (tf32 mma, causal block skip) ====
__global__ __launch_bounds__(256) void scores_tf32(
    const float* __restrict__ q, const float* __restrict__ k,
    float* __restrict__ attn, float scale)
{
    const int bx = blockIdx.x, by = blockIdx.y;
    if (bx > by) return;
    const int bh = blockIdx.z, b = bh >> 4, h = bh & 15, hk = h >> 2;

    __shared__ unsigned Qs[128][40];   // [i][d]
    __shared__ unsigned Ks[128][40];   // [j][d]
    const int t = threadIdx.x, lane = t & 31, w = t >> 5;
    const int wm = w >> 2, wn = w & 3;
    const int gid = lane >> 2, tg = lane & 3;
    const int ar = t >> 1, ac = (t & 1) * 16;

    const float* qp = q + (size_t)b*SEQ*DM  + (size_t)(by*128 + ar)*DM  + h*HD  + ac;
    const float* kp = k + (size_t)b*SEQ*KVD + (size_t)(bx*128 + ar)*KVD + hk*HD + ac;

    float acc[4][4][4];
    #pragma unroll
    for (int i=0;i<4;i++)
        #pragma unroll
        for (int j=0;j<4;j++)
            #pragma unroll
            for (int v=0;v<4;v++) acc[i][j][v]=0.f;

    float4 pq[4], pk[4];
    #pragma unroll
    for (int i=0;i<4;i++) pq[i] = *(const float4*)(qp + i*4);
    #pragma unroll
    for (int i=0;i<4;i++) pk[i] = *(const float4*)(kp + i*4);

    for (int it = 0; it < 4; ++it) {               // HD/32 = 4
        #pragma unroll
        for (int i=0;i<4;i++)
            *(uint4*)&Qs[ar][ac + i*4] =
                make_uint4(f2tf(pq[i].x),f2tf(pq[i].y),f2tf(pq[i].z),f2tf(pq[i].w));
        #pragma unroll
        for (int i=0;i<4;i++)
            *(uint4*)&Ks[ar][ac + i*4] =
                make_uint4(f2tf(pk[i].x),f2tf(pk[i].y),f2tf(pk[i].z),f2tf(pk[i].w));
        __syncthreads();
        if (it + 1 < 4) {
            #pragma unroll
            for (int i=0;i<4;i++) pq[i] = *(const float4*)(qp + (it+1)*32 + i*4);
            #pragma unroll
            for (int i=0;i<4;i++) pk[i] = *(const float4*)(kp + (it+1)*32 + i*4);
        }
        #pragma unroll
        for (int ks=0; ks<4; ++ks){
            unsigned af[4][4], bf[4][2];
            #pragma unroll
            for (int mt=0;mt<4;mt++){
                const int r = wm*64 + mt*16 + gid, c = ks*8 + tg;
                af[mt][0]=Qs[r][c];   af[mt][1]=Qs[r+8][c];
                af[mt][2]=Qs[r][c+4]; af[mt][3]=Qs[r+8][c+4];
            }
            #pragma unroll
            for (int nt=0;nt<4;nt++){
                const int jr = wn*32 + nt*8 + gid, c = ks*8 + tg;
                bf[nt][0]=Ks[jr][c]; bf[nt][1]=Ks[jr][c+4];
            }
            #pragma unroll
            for (int mt=0;mt<4;mt++)
                #pragma unroll
                for (int nt=0;nt<4;nt++)
                    mma_tf32(acc[mt][nt], af[mt], bf[nt]);
        }
        __syncthreads();
    }

    #pragma unroll
    for (int mt=0;mt<4;mt++){
        const int r = by*128 + wm*64 + mt*16 + gid;
        #pragma unroll
        for (int nt=0;nt<4;nt++){
            const int cn = bx*128 + wn*32 + nt*8 + tg*2;
            float* p0 = attn + ((size_t)bh*SEQ + r)*SEQ + cn;
            *(float2*)p0 = make_float2(acc[mt][nt][0]*scale, acc[mt][nt][1]*scale);
            float* p1 = attn + ((size_t)bh*SEQ + r + 8)*SEQ + cn;
            *(float2*)p1 = make_float2(acc[mt][nt][2]*scale, acc[mt][nt][3]*scale);
        }
    }
}

// ---------------- row softmax, causal zeros above diagonal ------------------
__global__ __launch_bounds__(256) void softmax_kernel(float* __restrict__ attn)
{
    const int row = blockIdx.x;
    const int i = row & (SEQ - 1);
    const int len = i + 1;
    float* p = attn + (size_t)row * SEQ;
    const int t = threadIdx.x;
    __shared__ float red[256];

    float vals[8];
    float m = -INFINITY;
    #pragma unroll
    for (int c = 0; c < 8; c++) {
        int j = c * 256 + t;
        if (j < len) { vals[c] = p[j]; m = fmaxf(m, vals[c]); }
    }
    red[t] = m; __syncthreads();
    for (int s = 128; s > 0; s >>= 1) {
        if (t < s) red[t] = fmaxf(red[t], red[t + s]);
        __syncthreads();
    }
    m = red[0]; __syncthreads();

    float l = 0.f;
    #pragma unroll
    for (int c = 0; c < 8; c++) {
        int j = c * 256 + t;
        if (j < len) { float e = __expf(vals[c] - m); vals[c] = e; l += e; }
    }
    red[t] = l; __syncthreads();
    for (int s = 128; s > 0; s >>= 1) {
        if (t < s) red[t] += red[t + s];
        __syncthreads();
    }
    const float inv = 1.0f / red[0];

    #pragma unroll
    for (int c = 0; c < 8; c++) {
        int j = c * 256 + t;
        if (j < len) p[j] = vals[c] * inv;
    }
    for (int j = len + t; j < SEQ; j += 256) p[j] = 0.f;
}

// ======= out_h = attn @ v (tf32 mma, causal K truncation) ===================
__global__ __launch_bounds__(256) void attnv_tf32(
    const float* __restrict__ attn, const float* __restrict__ v,
    float* __restrict__ ao)
{
    const int bh = blockIdx.y, b = bh >> 4, h = bh & 15, hk = h >> 2;
    const int i0 = blockIdx.x * 128;

    __shared__ unsigned Ps[128][40];   // [i][j]
    __shared__ unsigned Vs[32][136];   // [j][d]
    const int t = threadIdx.x, lane = t & 31, w = t >> 5;
    const int wm = w >> 2, wn = w & 3;
    const int gid = lane >> 2, tg = lane & 3;
    const int ar = t >> 1, ac = (t & 1) * 16;
    const int br = t >> 3, bc = (t & 7) * 16;

    const float* pp = attn + ((size_t)bh*SEQ + i0 + ar)*SEQ + ac;
    const float* vp = v + (size_t)b*SEQ*KVD + (size_t)br*KVD + hk*HD + bc;

    float acc[4][4][4];
    #pragma unroll
    for (int i=0;i<4;i++)
        #pragma unroll
        for (int j=0;j<4;j++)
            #pragma unroll
            for (int vv=0;vv<4;vv++) acc[i][j][vv]=0.f;

    float4 pa[4], pb[4];
    #pragma unroll
    for (int i=0;i<4;i++) pa[i] = *(const float4*)(pp + i*4);
    #pragma unroll
    for (int i=0;i<4;i++) pb[i] = *(const float4*)(vp + i*4);

    const int niter = (i0 + 128) >> 5;
    for (int it = 0; it < niter; ++it) {
        #pragma unroll
        for (int i=0;i<4;i++)
            *(uint4*)&Ps[ar][ac + i*4] =
                make_uint4(f2tf(pa[i].x),f2tf(pa[i].y),f2tf(pa[i].z),f2tf(pa[i].w));
        #pragma unroll
        for (int i=0;i<4;i++)
            *(uint4*)&Vs[br][bc + i*4] =
                make_uint4(f2tf(pb[i].x),f2tf(pb[i].y),f2tf(pb[i].z),f2tf(pb[i].w));
        __syncthreads();
        if (it + 1 < niter) {
            #pragma unroll
            for (int i=0;i<4;i++) pa[i] = *(const float4*)(pp + (it+1)*32 + i*4);
            #pragma unroll
            for (int i=0;i<4;i++) pb[i] = *(const float4*)(vp + (size_t)(it+1)*32*KVD + i*4);
        }
        #pragma unroll
        for (int ks=0; ks<4; ++ks){
            unsigned af[4][4], bf[4][2];
            #pragma unroll
            for (int mt=0;mt<4;mt++){
                const int r = wm*64 + mt*16 + gid, c = ks*8 + tg;
                af[mt][0]=Ps[r][c];   af[mt][1]=Ps[r+8][c];
                af[mt][2]=Ps[r][c+4]; af[mt][3]=Ps[r+8][c+4];
            }
            #pragma unroll
            for (int nt=0;nt<4;nt++){
                const int n = wn*32 + nt*8 + gid, kk = ks*8 + tg;
                bf[nt][0]=Vs[kk][n]; bf[nt][1]=Vs[kk+4][n];
            }
            #pragma unroll
            for (int mt=0;mt<4;mt++)
                #pragma unroll
                for (int nt=0;nt<4;nt++)
                    mma_tf32(acc[mt][nt], af[mt], bf[nt]);
        }
        __syncthreads();
    }

    #pragma unroll
    for (int mt=0;mt<4;mt++){
        const int r = i0 + wm*64 + mt*16 + gid;
        #pragma unroll
        for (int nt=0;nt<4;nt++){
            const int cn = wn*32 + nt*8 + tg*2;
            float* p0 = ao + ((size_t)b*SEQ + r)*DM + h*HD + cn;
            *(float2*)p0 = make_float2(acc[mt][nt][0], acc[mt][nt][1]);
            float* p1 = ao + ((size_t)b*SEQ + r + 8)*DM + h*HD + cn;
            *(float2*)p1 = make_float2(acc[mt][nt][2], acc[mt][nt][3]);
        }
    }
}

extern "C" void kernel_launch(void* const* d_in, const int* in_sizes, int n_in,
                              void* d_out, int out_size)
{
    const float* x  = (const float*)d_in[0];
    const float* fc = (const float*)d_in[1];
    const float* fs = (const float*)d_in[2];
    const float* wq = (const float*)d_in[3];
    const float* bq = (const float*)d_in[4];
    const float* wk = (const float*)d_in[5];
    const float* bk = (const float*)d_in[6];
    const float* wv = (const float*)d_in[7];
    const float* bv = (const float*)d_in[8];
    const float* wo = (const float*)d_in[9];

    float* outp = (float*)d_out;
    float* attn = outp + (size_t)BSZ * SEQ * DM;

    float *qb, *kb, *vb, *aob;
    cudaGetSymbolAddress((void**)&qb,  g_q);
    cudaGetSymbolAddress((void**)&kb,  g_k);
    cudaGetSymbolAddress((void**)&vb,  g_v);
    cudaGetSymbolAddress((void**)&aob, g_ao);

    const float scale = 1.0f / sqrtf((float)DM);

    gemm_tf32<<<dim3(DM / 128, MROWS / 128), 256>>>(x, wq, bq, qb, MROWS, DM, DM);
    gemm_tf32<<<dim3(KVD / 128, MROWS / 128), 256>>>(x, wk, bk, kb, MROWS, KVD, DM);
    gemm_tf32<<<dim3(KVD / 128, MROWS / 128), 256>>>(x, wv, bv, vb, MROWS, KVD, DM);

    {
        int totq = BSZ * SEQ * HQ * 64;
        rope_kernel<<<totq / 256, 256>>>(qb, fc, fs, HQ, totq);
        int totk = BSZ * SEQ * HKV * 64;
        rope_kernel<<<totk / 256, 256>>>(kb, fc, fs, HKV, totk);
    }

    scores_tf32<<<dim3(SEQ / 128, SEQ / 128, BSZ * HQ), 256>>>(qb, kb, attn, scale);
    softmax_kernel<<<BSZ * HQ * SEQ, 256>>>(attn);
    attnv_tf32<<<dim3(SEQ / 128, BSZ * HQ), 256>>>(attn, vb, aob);

    gemm_tf32<<<dim3(DM / 128, MROWS / 128), 256>>>(aob, wo, nullptr, outp, MROWS, DM, DM);
}

// round 4
// speedup vs baseline: 2.7936x; 1.3717x over previous
#include <cuda_runtime.h>
#include <cuda_fp16.h>
#include <math.h>
#include <stdint.h>

#define BSZ 2
#define SEQ 2048
#define DM  2048
#define HQ  16
#define HKV 4
#define HD  128
#define MROWS (BSZ*SEQ)        // 4096
#define KVD (HKV*HD)           // 512

// ---------------- persistent scratch (no runtime allocs) -------------------
__device__ __half g_xh [(size_t)MROWS*DM];
__device__ __half g_qh [(size_t)MROWS*DM];
__device__ __half g_kh [(size_t)MROWS*KVD];
__device__ __half g_vh [(size_t)MROWS*KVD];
__device__ __half g_vt [(size_t)BSZ*HKV*HD*SEQ];   // [b][hk][d][s]
__device__ __half g_aoh[(size_t)MROWS*DM];
__device__ __half g_wqt[(size_t)DM*DM];            // [N][K]
__device__ __half g_wkt[(size_t)KVD*DM];
__device__ __half g_wvt[(size_t)KVD*DM];
__device__ __half g_wot[(size_t)DM*DM];

// ---------------- helpers ---------------------------------------------------
__device__ __forceinline__ uint32_t pack2(float lo, float hi){
    __half2 h = __floats2half2_rn(lo, hi);
    return *reinterpret_cast<uint32_t*>(&h);
}
__device__ __forceinline__ uint32_t smem_u32(const void* p){
    uint32_t a;
    asm("{ .reg .u64 t; cvta.to.shared.u64 t, %1; cvt.u32.u64 %0, t; }"
        : "=r"(a) : "l"(p));
    return a;
}
__device__ __forceinline__ void ldsm_x4(uint32_t* r, uint32_t addr){
    asm volatile("ldmatrix.sync.aligned.m8n8.x4.shared.b16 {%0,%1,%2,%3}, [%4];"
        : "=r"(r[0]), "=r"(r[1]), "=r"(r[2]), "=r"(r[3]) : "r"(addr));
}
__device__ __forceinline__ void ldsm_x2(uint32_t* r, uint32_t addr){
    asm volatile("ldmatrix.sync.aligned.m8n8.x2.shared.b16 {%0,%1}, [%2];"
        : "=r"(r[0]), "=r"(r[1]) : "r"(addr));
}
__device__ __forceinline__ void mma_f16(float* d, const uint32_t* a, const uint32_t* b){
    asm volatile("mma.sync.aligned.m16n8k16.row.col.f32.f16.f16.f32 "
        "{%0,%1,%2,%3}, {%4,%5,%6,%7}, {%8,%9}, {%0,%1,%2,%3};"
        : "+f"(d[0]), "+f"(d[1]), "+f"(d[2]), "+f"(d[3])
        : "r"(a[0]), "r"(a[1]), "r"(a[2]), "r"(a[3]), "r"(b[0]), "r"(b[1]));
}

// ============ core: 128x128 block tile, D = A[M,K] @ B[N,K]^T ===============
// 8 warps (2m x 4n), warp tile 64x32, kTile 32, smem stride 40 halves
// AF: 0 -> A is half, 1 -> A is float (converted in loader)
// CF: 0 -> C half, 1 -> C float
template<int AF, int CF>
__device__ __forceinline__ void tc_core(
    const void* Av, int lda, const __half* __restrict__ B, int ldb,
    void* Cv, int ldc, const float* __restrict__ bias, float scale, int niter)
{
    __shared__ __half As[128*40];
    __shared__ __half Bs[128*40];
    const int t = threadIdx.x, lane = t & 31, w = t >> 5;
    const int wm = w >> 2, wn = w & 3, gid = lane >> 2, tg = lane & 3;
    const int row = t >> 1, cg = (t & 1) * 16;

    float acc[4][4][4];
    #pragma unroll
    for (int i=0;i<4;i++)
        #pragma unroll
        for (int j=0;j<4;j++)
            #pragma unroll
            for (int v=0;v<4;v++) acc[i][j][v]=0.f;

    const __half* Ah  = (const __half*)Av + (size_t)row * lda + cg;
    const float*  Afp = (const float*)Av + (size_t)row * lda + cg;
    const __half* Bp  = B + (size_t)row * ldb + cg;

    uint4 ra[2], rb[2];
    float4 rf[4];
    if (AF == 0) {
        ra[0] = *(const uint4*)Ah; ra[1] = *(const uint4*)(Ah + 8);
    } else {
        rf[0] = *(const float4*)Afp;      rf[1] = *(const float4*)(Afp + 4);
        rf[2] = *(const float4*)(Afp+8);  rf[3] = *(const float4*)(Afp + 12);
    }
    rb[0] = *(const uint4*)Bp; rb[1] = *(const uint4*)(Bp + 8);

    uint4* AsW = (uint4*)&As[row * 40 + cg];
    uint4* BsW = (uint4*)&Bs[row * 40 + cg];

    const uint32_t aAddr = smem_u32(As) +
        (((wm*64 + (lane & 15)) * 40 + ((lane >> 4) << 3)) << 1);
    const uint32_t bAddr = smem_u32(Bs) +
        (((wn*32 + (lane & 7)) * 40 + (((lane >> 3) & 1) << 3)) << 1);

    for (int it = 0; it < niter; ++it) {
        if (AF == 0) {
            AsW[0] = ra[0]; AsW[1] = ra[1];
        } else {
            AsW[0] = make_uint4(pack2(rf[0].x, rf[0].y), pack2(rf[0].z, rf[0].w),
                                pack2(rf[1].x, rf[1].y), pack2(rf[1].z, rf[1].w));
            AsW[1] = make_uint4(pack2(rf[2].x, rf[2].y), pack2(rf[2].z, rf[2].w),
                                pack2(rf[3].x, rf[3].y), pack2(rf[3].z, rf[3].w));
        }
        BsW[0] = rb[0]; BsW[1] = rb[1];
        __syncthreads();

        if (it + 1 < niter) {
            const int off = (it + 1) * 32;
            if (AF == 0) {
                ra[0] = *(const uint4*)(Ah + off);
                ra[1] = *(const uint4*)(Ah + off + 8);
            } else {
                rf[0] = *(const float4*)(Afp + off);
                rf[1] = *(const float4*)(Afp + off + 4);
                rf[2] = *(const float4*)(Afp + off + 8);
                rf[3] = *(const float4*)(Afp + off + 12);
            }
            rb[0] = *(const uint4*)(Bp + off);
            rb[1] = *(const uint4*)(Bp + off + 8);
        }

        #pragma unroll
        for (int c = 0; c < 2; ++c) {
            uint32_t af[4][4], bf[4][2];
            #pragma unroll
            for (int mt = 0; mt < 4; ++mt)
                ldsm_x4(af[mt], aAddr + mt * 1280 + c * 32);
            #pragma unroll
            for (int nt = 0; nt < 4; ++nt)
                ldsm_x2(bf[nt], bAddr + nt * 640 + c * 32);
            #pragma unroll
            for (int mt = 0; mt < 4; ++mt)
                #pragma unroll
                for (int nt = 0; nt < 4; ++nt)
                    mma_f16(acc[mt][nt], af[mt], bf[nt]);
        }
        __syncthreads();
    }

    #pragma unroll
    for (int mt = 0; mt < 4; ++mt) {
        const int r0 = wm*64 + mt*16 + gid;
        #pragma unroll
        for (int nt = 0; nt < 4; ++nt) {
            const int cn = wn*32 + nt*8 + 2*tg;
            float b0 = 0.f, b1 = 0.f;
            if (bias) { b0 = bias[cn]; b1 = bias[cn+1]; }
            const float v00 = acc[mt][nt][0]*scale + b0;
            const float v01 = acc[mt][nt][1]*scale + b1;
            const float v10 = acc[mt][nt][2]*scale + b0;
            const float v11 = acc[mt][nt][3]*scale + b1;
            if (CF == 1) {
                float* C = (float*)Cv;
                *(float2*)(C + (size_t)r0*ldc + cn)     = make_float2(v00, v01);
                *(float2*)(C + (size_t)(r0+8)*ldc + cn) = make_float2(v10, v11);
            } else {
                __half* C = (__half*)Cv;
                *(uint32_t*)(C + (size_t)r0*ldc + cn)     = pack2(v00, v01);
                *(uint32_t*)(C + (size_t)(r0+8)*ldc + cn) = pack2(v10, v11);
            }
        }
    }
}

// ---------------- GEMM wrappers ---------------------------------------------
__global__ __launch_bounds__(256, 2) void k_proj(
    const __half* __restrict__ X, const __half* __restrict__ Wt,
    const float* __restrict__ bias, __half* __restrict__ C, int N)
{
    const __half* A = X + (size_t)blockIdx.y * 128 * DM;
    const __half* B = Wt + (size_t)blockIdx.x * 128 * DM;
    __half* Cp = C + (size_t)blockIdx.y * 128 * N + blockIdx.x * 128;
    tc_core<0,0>(A, DM, B, DM, Cp, N,
                 bias ? bias + blockIdx.x * 128 : (const float*)0, 1.0f, DM/32);
}

__global__ __launch_bounds__(256, 2) void k_proj_o(
    const __half* __restrict__ X, const __half* __restrict__ Wt,
    float* __restrict__ C)
{
    const __half* A = X + (size_t)blockIdx.y * 128 * DM;
    const __half* B = Wt + (size_t)blockIdx.x * 128 * DM;
    float* Cp = C + (size_t)blockIdx.y * 128 * DM + blockIdx.x * 128;
    tc_core<0,1>(A, DM, B, DM, Cp, DM, (const float*)0, 1.0f, DM/32);
}

__global__ __launch_bounds__(256, 2) void k_scores(
    const __half* __restrict__ q, const __half* __restrict__ k,
    float* __restrict__ attn, float scale)
{
    if (blockIdx.x > blockIdx.y) return;          // causal block skip
    const int bh = blockIdx.z, b = bh >> 4, h = bh & 15, hk = h >> 2;
    const __half* A = q + ((size_t)b*SEQ + blockIdx.y*128) * DM  + h*HD;
    const __half* B = k + ((size_t)b*SEQ + blockIdx.x*128) * KVD + hk*HD;
    float* C = attn + ((size_t)bh*SEQ + blockIdx.y*128)*SEQ + blockIdx.x*128;
    tc_core<0,1>(A, DM, B, KVD, C, SEQ, (const float*)0, scale, HD/32);
}

__global__ __launch_bounds__(256, 2) void k_attnv(
    const float* __restrict__ attn, const __half* __restrict__ vt,
    __half* __restrict__ ao)
{
    const int bh = blockIdx.y, b = bh >> 4, h = bh & 15, hk = h >> 2;
    const int i0 = blockIdx.x * 128;
    const float* A = attn + ((size_t)bh*SEQ + i0)*SEQ;          // [i][j] fp32
    const __half* B = vt + (size_t)(b*HKV + hk)*HD*SEQ;         // [d][j]
    __half* C = ao + ((size_t)b*SEQ + i0)*DM + h*HD;
    tc_core<1,0>(A, SEQ, B, SEQ, C, DM, (const float*)0, 1.0f, (i0+128)/32);
}

// ---------------- converts / transposes -------------------------------------
__global__ void k_cvt_x(const float* __restrict__ x, __half* __restrict__ xh, int n4)
{
    int i = blockIdx.x * blockDim.x + threadIdx.x;
    if (i >= n4) return;
    float4 v = ((const float4*)x)[i];
    ((uint2*)xh)[i] = make_uint2(pack2(v.x, v.y), pack2(v.z, v.w));
}

__global__ __launch_bounds__(256) void k_cvt_w(
    const float* __restrict__ src, __half* __restrict__ dst, int N, int K)
{
    __shared__ float tile[32][33];
    const int tx = threadIdx.x & 31, ty = threadIdx.x >> 5;
    const int r0 = blockIdx.y * 32, c0 = blockIdx.x * 32;   // r over K, c over N
    #pragma unroll
    for (int i = 0; i < 32; i += 8)
        tile[ty + i][tx] = src[(size_t)(r0 + ty + i) * N + c0 + tx];
    __syncthreads();
    #pragma unroll
    for (int i = 0; i < 32; i += 8)
        dst[(size_t)(c0 + ty + i) * K + r0 + tx] = __float2half(tile[tx][ty + i]);
}

__global__ __launch_bounds__(256) void k_transpose_v(
    const __half* __restrict__ v, __half* __restrict__ vt)
{
    __shared__ __half tile[32][33];
    const int z = blockIdx.z, b = z >> 2, hk = z & 3;
    const int tx = threadIdx.x & 31, ty = threadIdx.x >> 5;
    const int r0 = blockIdx.y * 32, c0 = blockIdx.x * 32;   // r over s, c over d
    #pragma unroll
    for (int i = 0; i < 32; i += 8)
        tile[ty + i][tx] = v[((size_t)b*SEQ + r0 + ty + i) * KVD + hk*HD + c0 + tx];
    __syncthreads();
    #pragma unroll
    for (int i = 0; i < 32; i += 8)
        vt[((size_t)(b*HKV + hk)*HD + c0 + ty + i) * SEQ + r0 + tx] = tile[tx][ty + i];
}

// ---------------- RoPE in-place on half (b,s,nh,128) ------------------------
__global__ void rope_h(__half* __restrict__ buf,
                       const float* __restrict__ cosb,
                       const float* __restrict__ sinb,
                       int nh, int total)
{
    int idx = blockIdx.x * blockDim.x + threadIdx.x;
    if (idx >= total) return;
    int pair = idx & 63;
    int h = (idx >> 6) % nh;
    int s = (idx / (64 * nh)) % SEQ;
    int b = idx / (64 * nh * SEQ);
    size_t base = (((size_t)b * SEQ + s) * nh + h) * HD;
    __half2* p2 = (__half2*)(buf + base);
    float2 xv = __half22float2(p2[pair]);
    float c  = cosb[s * 64 + pair];
    float sn = sinb[s * 64 + pair];
    p2[pair] = __floats2half2_rn(xv.x * c - xv.y * sn, xv.x * sn + xv.y * c);
}

// ---------------- row softmax, causal zero-fill (fp32) ----------------------
__global__ __launch_bounds__(256) void softmax_kernel(float* __restrict__ attn)
{
    const int row = blockIdx.x;
    const int i = row & (SEQ - 1);
    const int len = i + 1;
    float* p = attn + (size_t)row * SEQ;
    const int t = threadIdx.x;
    __shared__ float red[256];

    float vals[8];
    float m = -INFINITY;
    #pragma unroll
    for (int c = 0; c < 8; c++) {
        int j = c * 256 + t;
        if (j < len) { vals[c] = p[j]; m = fmaxf(m, vals[c]); }
    }
    red[t] = m; __syncthreads();
    for (int s = 128; s > 0; s >>= 1) {
        if (t < s) red[t] = fmaxf(red[t], red[t + s]);
        __syncthreads();
    }
    m = red[0]; __syncthreads();

    float l = 0.f;
    #pragma unroll
    for (int c = 0; c < 8; c++) {
        int j = c * 256 + t;
        if (j < len) { float e = __expf(vals[c] - m); vals[c] = e; l += e; }
    }
    red[t] = l; __syncthreads();
    for (int s = 128; s > 0; s >>= 1) {
        if (t < s) red[t] += red[t + s];
        __syncthreads();
    }
    const float inv = 1.0f / red[0];

    #pragma unroll
    for (int c = 0; c < 8; c++) {
        int j = c * 256 + t;
        if (j < len) p[j] = vals[c] * inv;
    }
    for (int j = len + t; j < SEQ; j += 256) p[j] = 0.f;
}

// ---------------- launch ------------------------------------------------------
extern "C" void kernel_launch(void* const* d_in, const int* in_sizes, int n_in,
                              void* d_out, int out_size)
{
    const float* x  = (const float*)d_in[0];
    const float* fc = (const float*)d_in[1];
    const float* fs = (const float*)d_in[2];
    const float* wq = (const float*)d_in[3];
    const float* bq = (const float*)d_in[4];
    const float* wk = (const float*)d_in[5];
    const float* bk = (const float*)d_in[6];
    const float* wv = (const float*)d_in[7];
    const float* bv = (const float*)d_in[8];
    const float* wo = (const float*)d_in[9];

    float* outp = (float*)d_out;
    float* attn = outp + (size_t)BSZ * SEQ * DM;

    __half *xh, *qh, *kh, *vh, *vt, *aoh, *wqt, *wkt, *wvt, *wot;
    cudaGetSymbolAddress((void**)&xh,  g_xh);
    cudaGetSymbolAddress((void**)&qh,  g_qh);
    cudaGetSymbolAddress((void**)&kh,  g_kh);
    cudaGetSymbolAddress((void**)&vh,  g_vh);
    cudaGetSymbolAddress((void**)&vt,  g_vt);
    cudaGetSymbolAddress((void**)&aoh, g_aoh);
    cudaGetSymbolAddress((void**)&wqt, g_wqt);
    cudaGetSymbolAddress((void**)&wkt, g_wkt);
    cudaGetSymbolAddress((void**)&wvt, g_wvt);
    cudaGetSymbolAddress((void**)&wot, g_wot);

    const float scale = 1.0f / sqrtf((float)DM);

    // input/weight conversion (fp32 -> fp16, weights also transposed to [N][K])
    k_cvt_x<<<(MROWS*DM/4 + 255)/256, 256>>>(x, xh, MROWS*DM/4);
    k_cvt_w<<<dim3(DM/32,  DM/32), 256>>>(wq, wqt, DM,  DM);
    k_cvt_w<<<dim3(KVD/32, DM/32), 256>>>(wk, wkt, KVD, DM);
    k_cvt_w<<<dim3(KVD/32, DM/32), 256>>>(wv, wvt, KVD, DM);
    k_cvt_w<<<dim3(DM/32,  DM/32), 256>>>(wo, wot, DM,  DM);

    // projections (fp16 tensor core)
    k_proj<<<dim3(DM/128,  MROWS/128), 256>>>(xh, wqt, bq, qh, DM);
    k_proj<<<dim3(KVD/128, MROWS/128), 256>>>(xh, wkt, bk, kh, KVD);
    k_proj<<<dim3(KVD/128, MROWS/128), 256>>>(xh, wvt, bv, vh, KVD);

    // rope + V transpose
    {
        int totq = BSZ * SEQ * HQ * 64;
        rope_h<<<totq / 256, 256>>>(qh, fc, fs, HQ, totq);
        int totk = BSZ * SEQ * HKV * 64;
        rope_h<<<totk / 256, 256>>>(kh, fc, fs, HKV, totk);
    }
    k_transpose_v<<<dim3(HD/32, SEQ/32, BSZ*HKV), 256>>>(vh, vt);

    // attention
    k_scores<<<dim3(SEQ/128, SEQ/128, BSZ*HQ), 256>>>(qh, kh, attn, scale);
    softmax_kernel<<<BSZ * HQ * SEQ, 256>>>(attn);
    k_attnv<<<dim3(SEQ/128, BSZ*HQ), 256>>>(attn, vt, aoh);

    // output projection
    k_proj_o<<<dim3(DM/128, MROWS/128), 256>>>(aoh, wot, outp);
}

// round 5
// speedup vs baseline: 4.5525x; 1.6296x over previous
#include <cuda_runtime.h>
#include <cuda_fp16.h>
#include <math.h>
#include <stdint.h>

#define BSZ 2
#define SEQ 2048
#define DM  2048
#define HQ  16
#define HKV 4
#define HD  128
#define MROWS (BSZ*SEQ)        // 4096
#define KVD (HKV*HD)           // 512

// ---------------- persistent scratch ----------------------------------------
__device__ __half g_xh [(size_t)MROWS*DM];
__device__ __half g_qh [(size_t)MROWS*DM];
__device__ __half g_kh [(size_t)MROWS*KVD];
__device__ __half g_vh [(size_t)MROWS*KVD];
__device__ __half g_vt [(size_t)BSZ*HKV*HD*SEQ];   // [b][hk][d][s]
__device__ __half g_aoh[(size_t)MROWS*DM];
__device__ __half g_wqt[(size_t)DM*DM];            // [N][K]
__device__ __half g_wkt[(size_t)KVD*DM];
__device__ __half g_wvt[(size_t)KVD*DM];
__device__ __half g_wot[(size_t)DM*DM];

// ---------------- helpers ---------------------------------------------------
__device__ __forceinline__ uint32_t pack2(float lo, float hi){
    __half2 h = __floats2half2_rn(lo, hi);
    return *reinterpret_cast<uint32_t*>(&h);
}
__device__ __forceinline__ uint32_t smem_u32(const void* p){
    uint32_t a;
    asm("{ .reg .u64 t; cvta.to.shared.u64 t, %1; cvt.u32.u64 %0, t; }"
        : "=r"(a) : "l"(p));
    return a;
}
__device__ __forceinline__ void cp16(uint32_t dst, const void* src){
    asm volatile("cp.async.cg.shared.global [%0], [%1], 16;"
        :: "r"(dst), "l"(src) : "memory");
}
#define CP_COMMIT() asm volatile("cp.async.commit_group;" ::: "memory")
#define CP_WAIT0()  asm volatile("cp.async.wait_group 0;" ::: "memory")

__device__ __forceinline__ void ldsm_x4(uint32_t* r, uint32_t addr){
    asm volatile("ldmatrix.sync.aligned.m8n8.x4.shared.b16 {%0,%1,%2,%3}, [%4];"
        : "=r"(r[0]), "=r"(r[1]), "=r"(r[2]), "=r"(r[3]) : "r"(addr));
}
__device__ __forceinline__ void ldsm_x2(uint32_t* r, uint32_t addr){
    asm volatile("ldmatrix.sync.aligned.m8n8.x2.shared.b16 {%0,%1}, [%2];"
        : "=r"(r[0]), "=r"(r[1]) : "r"(addr));
}
__device__ __forceinline__ void mma_f16(float* d, const uint32_t* a, const uint32_t* b){
    asm volatile("mma.sync.aligned.m16n8k16.row.col.f32.f16.f16.f32 "
        "{%0,%1,%2,%3}, {%4,%5,%6,%7}, {%8,%9}, {%0,%1,%2,%3};"
        : "+f"(d[0]), "+f"(d[1]), "+f"(d[2]), "+f"(d[3])
        : "r"(a[0]), "r"(a[1]), "r"(a[2]), "r"(a[3]), "r"(b[0]), "r"(b[1]));
}

// ============ fp16 core: 128x128 tile, D = A[M,K] @ B[N,K]^T ================
// 8 warps (2m x 4n), warp 64x32, kTile 32, cp.async 2-stage, 1 sync/iter.
// CF: 0 -> C half, 1 -> C float.  cosb!=null -> fused RoPE epilogue.
template<int CF>
__device__ __forceinline__ void tc_fp16(
    const __half* __restrict__ A, int lda, const __half* __restrict__ B, int ldb,
    void* Cv, int ldc, const float* __restrict__ bias, float scale, int niter,
    const float* __restrict__ cosb, const float* __restrict__ sinb, int srow)
{
    __shared__ __half As[2][128*40];
    __shared__ __half Bs[2][128*40];
    const int t = threadIdx.x, lane = t & 31, w = t >> 5;
    const int wm = w >> 2, wn = w & 3, gid = lane >> 2, tg = lane & 3;
    const int row = t >> 1, ch = (t & 1) * 16;

    float acc[4][4][4];
    #pragma unroll
    for (int i=0;i<4;i++)
        #pragma unroll
        for (int j=0;j<4;j++)
            #pragma unroll
            for (int v=0;v<4;v++) acc[i][j][v]=0.f;

    const __half* Ag = A + (size_t)row * lda + ch;
    const __half* Bg = B + (size_t)row * ldb + ch;
    uint32_t sa[2], sb[2];
    sa[0] = smem_u32(&As[0][row*40 + ch]);
    sa[1] = smem_u32(&As[1][row*40 + ch]);
    sb[0] = smem_u32(&Bs[0][row*40 + ch]);
    sb[1] = smem_u32(&Bs[1][row*40 + ch]);

    uint32_t aAddr[2], bAddr[2];
    #pragma unroll
    for (int s = 0; s < 2; ++s) {
        aAddr[s] = smem_u32(&As[s][0]) +
            (((wm*64 + (lane & 15)) * 40 + ((lane >> 4) << 3)) << 1);
        bAddr[s] = smem_u32(&Bs[s][0]) +
            (((wn*32 + (lane & 7)) * 40 + (((lane >> 3) & 1) << 3)) << 1);
    }

    // prologue: load k-iter 0 into stage 0
    cp16(sa[0], Ag);      cp16(sa[0] + 16, Ag + 8);
    cp16(sb[0], Bg);      cp16(sb[0] + 16, Bg + 8);
    CP_COMMIT();

    for (int it = 0; it < niter; ++it) {
        const int cur = it & 1;
        CP_WAIT0();
        __syncthreads();
        if (it + 1 < niter) {
            const int nxt = cur ^ 1;
            const __half* a = Ag + (size_t)(it + 1) * 32;
            const __half* b = Bg + (size_t)(it + 1) * 32;
            cp16(sa[nxt], a); cp16(sa[nxt] + 16, a + 8);
            cp16(sb[nxt], b); cp16(sb[nxt] + 16, b + 8);
            CP_COMMIT();
        }
        #pragma unroll
        for (int c = 0; c < 2; ++c) {
            uint32_t af[4][4], bf[4][2];
            #pragma unroll
            for (int mt = 0; mt < 4; ++mt)
                ldsm_x4(af[mt], aAddr[cur] + mt * 1280 + c * 32);
            #pragma unroll
            for (int nt = 0; nt < 4; ++nt)
                ldsm_x2(bf[nt], bAddr[cur] + nt * 640 + c * 32);
            #pragma unroll
            for (int mt = 0; mt < 4; ++mt)
                #pragma unroll
                for (int nt = 0; nt < 4; ++nt)
                    mma_f16(acc[mt][nt], af[mt], bf[nt]);
        }
    }

    #pragma unroll
    for (int mt = 0; mt < 4; ++mt) {
        const int r0 = wm*64 + mt*16 + gid;
        #pragma unroll
        for (int nt = 0; nt < 4; ++nt) {
            const int cn = wn*32 + nt*8 + 2*tg;
            float b0 = 0.f, b1 = 0.f;
            if (bias) { b0 = bias[cn]; b1 = bias[cn+1]; }
            float v00 = acc[mt][nt][0]*scale + b0;
            float v01 = acc[mt][nt][1]*scale + b1;
            float v10 = acc[mt][nt][2]*scale + b0;
            float v11 = acc[mt][nt][3]*scale + b1;
            if (cosb) {
                const int p = cn >> 1;
                const float c0 = cosb[(srow + r0) * 64 + p];
                const float s0 = sinb[(srow + r0) * 64 + p];
                const float c1 = cosb[(srow + r0 + 8) * 64 + p];
                const float s1 = sinb[(srow + r0 + 8) * 64 + p];
                float t0 = v00*c0 - v01*s0, t1 = v00*s0 + v01*c0;
                v00 = t0; v01 = t1;
                t0 = v10*c1 - v11*s1; t1 = v10*s1 + v11*c1;
                v10 = t0; v11 = t1;
            }
            if (CF == 1) {
                float* C = (float*)Cv;
                *(float2*)(C + (size_t)r0*ldc + cn)     = make_float2(v00, v01);
                *(float2*)(C + (size_t)(r0+8)*ldc + cn) = make_float2(v10, v11);
            } else {
                __half* C = (__half*)Cv;
                *(uint32_t*)(C + (size_t)r0*ldc + cn)     = pack2(v00, v01);
                *(uint32_t*)(C + (size_t)(r0+8)*ldc + cn) = pack2(v10, v11);
            }
        }
    }
}

// ============ attnv core (A fp32 converted in loader, from R4) ==============
__device__ __forceinline__ void tc_attnv_core(
    const float* __restrict__ Afp, int lda, const __half* __restrict__ B, int ldb,
    __half* __restrict__ C, int ldc, int niter)
{
    __shared__ __half As[128*40];
    __shared__ __half Bs[128*40];
    const int t = threadIdx.x, lane = t & 31, w = t >> 5;
    const int wm = w >> 2, wn = w & 3, gid = lane >> 2, tg = lane & 3;
    const int row = t >> 1, cg = (t & 1) * 16;

    float acc[4][4][4];
    #pragma unroll
    for (int i=0;i<4;i++)
        #pragma unroll
        for (int j=0;j<4;j++)
            #pragma unroll
            for (int v=0;v<4;v++) acc[i][j][v]=0.f;

    const float* Ap = Afp + (size_t)row * lda + cg;
    const __half* Bp = B + (size_t)row * ldb + cg;

    float4 rf[4]; uint4 rb[2];
    rf[0] = *(const float4*)Ap;       rf[1] = *(const float4*)(Ap + 4);
    rf[2] = *(const float4*)(Ap + 8); rf[3] = *(const float4*)(Ap + 12);
    rb[0] = *(const uint4*)Bp;        rb[1] = *(const uint4*)(Bp + 8);

    uint4* AsW = (uint4*)&As[row * 40 + cg];
    uint4* BsW = (uint4*)&Bs[row * 40 + cg];
    const uint32_t aAddr = smem_u32(As) +
        (((wm*64 + (lane & 15)) * 40 + ((lane >> 4) << 3)) << 1);
    const uint32_t bAddr = smem_u32(Bs) +
        (((wn*32 + (lane & 7)) * 40 + (((lane >> 3) & 1) << 3)) << 1);

    for (int it = 0; it < niter; ++it) {
        AsW[0] = make_uint4(pack2(rf[0].x, rf[0].y), pack2(rf[0].z, rf[0].w),
                            pack2(rf[1].x, rf[1].y), pack2(rf[1].z, rf[1].w));
        AsW[1] = make_uint4(pack2(rf[2].x, rf[2].y), pack2(rf[2].z, rf[2].w),
                            pack2(rf[3].x, rf[3].y), pack2(rf[3].z, rf[3].w));
        BsW[0] = rb[0]; BsW[1] = rb[1];
        __syncthreads();
        if (it + 1 < niter) {
            const int off = (it + 1) * 32;
            rf[0] = *(const float4*)(Ap + off);
            rf[1] = *(const float4*)(Ap + off + 4);
            rf[2] = *(const float4*)(Ap + off + 8);
            rf[3] = *(const float4*)(Ap + off + 12);
            rb[0] = *(const uint4*)(Bp + off);
            rb[1] = *(const uint4*)(Bp + off + 8);
        }
        #pragma unroll
        for (int c = 0; c < 2; ++c) {
            uint32_t af[4][4], bf[4][2];
            #pragma unroll
            for (int mt = 0; mt < 4; ++mt)
                ldsm_x4(af[mt], aAddr + mt * 1280 + c * 32);
            #pragma unroll
            for (int nt = 0; nt < 4; ++nt)
                ldsm_x2(bf[nt], bAddr + nt * 640 + c * 32);
            #pragma unroll
            for (int mt = 0; mt < 4; ++mt)
                #pragma unroll
                for (int nt = 0; nt < 4; ++nt)
                    mma_f16(acc[mt][nt], af[mt], bf[nt]);
        }
        __syncthreads();
    }

    #pragma unroll
    for (int mt = 0; mt < 4; ++mt) {
        const int r0 = wm*64 + mt*16 + gid;
        #pragma unroll
        for (int nt = 0; nt < 4; ++nt) {
            const int cn = wn*32 + nt*8 + 2*tg;
            *(uint32_t*)(C + (size_t)r0*ldc + cn) =
                pack2(acc[mt][nt][0], acc[mt][nt][1]);
            *(uint32_t*)(C + (size_t)(r0+8)*ldc + cn) =
                pack2(acc[mt][nt][2], acc[mt][nt][3]);
        }
    }
}

// ---------------- GEMM wrappers ---------------------------------------------
// fused QKV projection + RoPE: grid (24, 32). bx 0-15: Q head bx; 16-19: K; 20-23: V
__global__ __launch_bounds__(256) void k_qkv(
    const __half* __restrict__ xh,
    const __half* __restrict__ wqt, const __half* __restrict__ wkt,
    const __half* __restrict__ wvt,
    const float* __restrict__ bq, const float* __restrict__ bk,
    const float* __restrict__ bv,
    __half* __restrict__ qh, __half* __restrict__ kh, __half* __restrict__ vh,
    const float* __restrict__ cosb, const float* __restrict__ sinb)
{
    const int bx = blockIdx.x, by = blockIdx.y;
    const __half* A = xh + (size_t)by * 128 * DM;
    const int srow = (by & 15) * 128;
    if (bx < 16) {
        tc_fp16<0>(A, DM, wqt + (size_t)bx*128*DM, DM,
                   qh + (size_t)by*128*DM + bx*128, DM,
                   bq + bx*128, 1.0f, DM/32, cosb, sinb, srow);
    } else if (bx < 20) {
        const int c = bx - 16;
        tc_fp16<0>(A, DM, wkt + (size_t)c*128*DM, DM,
                   kh + (size_t)by*128*KVD + c*128, KVD,
                   bk + c*128, 1.0f, DM/32, cosb, sinb, srow);
    } else {
        const int c = bx - 20;
        tc_fp16<0>(A, DM, wvt + (size_t)c*128*DM, DM,
                   vh + (size_t)by*128*KVD + c*128, KVD,
                   bv + c*128, 1.0f, DM/32, (const float*)0, (const float*)0, 0);
    }
}

__global__ __launch_bounds__(256) void k_proj_o(
    const __half* __restrict__ X, const __half* __restrict__ Wt,
    float* __restrict__ C)
{
    tc_fp16<1>(X + (size_t)blockIdx.y*128*DM, DM,
               Wt + (size_t)blockIdx.x*128*DM, DM,
               C + (size_t)blockIdx.y*128*DM + blockIdx.x*128, DM,
               (const float*)0, 1.0f, DM/32, (const float*)0, (const float*)0, 0);
}

__global__ __launch_bounds__(256) void k_scores(
    const __half* __restrict__ q, const __half* __restrict__ k,
    float* __restrict__ attn, float scale)
{
    if (blockIdx.x > blockIdx.y) return;          // causal block skip
    const int bh = blockIdx.z, b = bh >> 4, h = bh & 15, hk = h >> 2;
    const __half* A = q + ((size_t)b*SEQ + blockIdx.y*128) * DM  + h*HD;
    const __half* B = k + ((size_t)b*SEQ + blockIdx.x*128) * KVD + hk*HD;
    float* C = attn + ((size_t)bh*SEQ + blockIdx.y*128)*SEQ + blockIdx.x*128;
    tc_fp16<1>(A, DM, B, KVD, C, SEQ, (const float*)0, scale, HD/32,
               (const float*)0, (const float*)0, 0);
}

__global__ __launch_bounds__(256) void k_attnv(
    const float* __restrict__ attn, const __half* __restrict__ vt,
    __half* __restrict__ ao)
{
    const int bh = blockIdx.y, b = bh >> 4, h = bh & 15, hk = h >> 2;
    const int i0 = blockIdx.x * 128;
    tc_attnv_core(attn + ((size_t)bh*SEQ + i0)*SEQ, SEQ,
                  vt + (size_t)(b*HKV + hk)*HD*SEQ, SEQ,
                  ao + ((size_t)b*SEQ + i0)*DM + h*HD, DM, (i0+128)/32);
}

// ---------------- converts / transposes -------------------------------------
__global__ void k_cvt_x(const float* __restrict__ x, __half* __restrict__ xh, int n4)
{
    int i = blockIdx.x * blockDim.x + threadIdx.x;
    if (i >= n4) return;
    float4 v = ((const float4*)x)[i];
    ((uint2*)xh)[i] = make_uint2(pack2(v.x, v.y), pack2(v.z, v.w));
}

__global__ __launch_bounds__(256) void k_cvt_w(
    const float* __restrict__ src, __half* __restrict__ dst, int N, int K)
{
    __shared__ float tile[32][33];
    const int tx = threadIdx.x & 31, ty = threadIdx.x >> 5;
    const int r0 = blockIdx.y * 32, c0 = blockIdx.x * 32;   // r over K, c over N
    #pragma unroll
    for (int i = 0; i < 32; i += 8)
        tile[ty + i][tx] = src[(size_t)(r0 + ty + i) * N + c0 + tx];
    __syncthreads();
    #pragma unroll
    for (int i = 0; i < 32; i += 8)
        dst[(size_t)(c0 + ty + i) * K + r0 + tx] = __float2half(tile[tx][ty + i]);
}

__global__ __launch_bounds__(256) void k_transpose_v(
    const __half* __restrict__ v, __half* __restrict__ vt)
{
    __shared__ __half tile[32][33];
    const int z = blockIdx.z, b = z >> 2, hk = z & 3;
    const int tx = threadIdx.x & 31, ty = threadIdx.x >> 5;
    const int r0 = blockIdx.y * 32, c0 = blockIdx.x * 32;   // r over s, c over d
    #pragma unroll
    for (int i = 0; i < 32; i += 8)
        tile[ty + i][tx] = v[((size_t)b*SEQ + r0 + ty + i) * KVD + hk*HD + c0 + tx];
    __syncthreads();
    #pragma unroll
    for (int i = 0; i < 32; i += 8)
        vt[((size_t)(b*HKV + hk)*HD + c0 + ty + i) * SEQ + r0 + tx] = tile[tx][ty + i];
}

// ---------------- row softmax, causal zero-fill (fp32) ----------------------
__global__ __launch_bounds__(256) void softmax_kernel(float* __restrict__ attn)
{
    const int row = blockIdx.x;
    const int i = row & (SEQ - 1);
    const int len = i + 1;
    float* p = attn + (size_t)row * SEQ;
    const int t = threadIdx.x;
    __shared__ float red[256];

    float vals[8];
    float m = -INFINITY;
    #pragma unroll
    for (int c = 0; c < 8; c++) {
        int j = c * 256 + t;
        if (j < len) { vals[c] = p[j]; m = fmaxf(m, vals[c]); }
    }
    red[t] = m; __syncthreads();
    for (int s = 128; s > 0; s >>= 1) {
        if (t < s) red[t] = fmaxf(red[t], red[t + s]);
        __syncthreads();
    }
    m = red[0]; __syncthreads();

    float l = 0.f;
    #pragma unroll
    for (int c = 0; c < 8; c++) {
        int j = c * 256 + t;
        if (j < len) { float e = __expf(vals[c] - m); vals[c] = e; l += e; }
    }
    red[t] = l; __syncthreads();
    for (int s = 128; s > 0; s >>= 1) {
        if (t < s) red[t] += red[t + s];
        __syncthreads();
    }
    const float inv = 1.0f / red[0];

    #pragma unroll
    for (int c = 0; c < 8; c++) {
        int j = c * 256 + t;
        if (j < len) p[j] = vals[c] * inv;
    }
    for (int j = len + t; j < SEQ; j += 256) p[j] = 0.f;
}

// ---------------- launch ------------------------------------------------------
extern "C" void kernel_launch(void* const* d_in, const int* in_sizes, int n_in,
                              void* d_out, int out_size)
{
    const float* x  = (const float*)d_in[0];
    const float* fc = (const float*)d_in[1];
    const float* fs = (const float*)d_in[2];
    const float* wq = (const float*)d_in[3];
    const float* bq = (const float*)d_in[4];
    const float* wk = (const float*)d_in[5];
    const float* bk = (const float*)d_in[6];
    const float* wv = (const float*)d_in[7];
    const float* bv = (const float*)d_in[8];
    const float* wo = (const float*)d_in[9];

    float* outp = (float*)d_out;
    float* attn = outp + (size_t)BSZ * SEQ * DM;

    __half *xh, *qh, *kh, *vh, *vt, *aoh, *wqt, *wkt, *wvt, *wot;
    cudaGetSymbolAddress((void**)&xh,  g_xh);
    cudaGetSymbolAddress((void**)&qh,  g_qh);
    cudaGetSymbolAddress((void**)&kh,  g_kh);
    cudaGetSymbolAddress((void**)&vh,  g_vh);
    cudaGetSymbolAddress((void**)&vt,  g_vt);
    cudaGetSymbolAddress((void**)&aoh, g_aoh);
    cudaGetSymbolAddress((void**)&wqt, g_wqt);
    cudaGetSymbolAddress((void**)&wkt, g_wkt);
    cudaGetSymbolAddress((void**)&wvt, g_wvt);
    cudaGetSymbolAddress((void**)&wot, g_wot);

    const float scale = 1.0f / sqrtf((float)DM);

    // conversions (launches 1-5)
    k_cvt_x<<<(MROWS*DM/4 + 255)/256, 256>>>(x, xh, MROWS*DM/4);
    k_cvt_w<<<dim3(DM/32,  DM/32), 256>>>(wq, wqt, DM,  DM);
    k_cvt_w<<<dim3(KVD/32, DM/32), 256>>>(wk, wkt, KVD, DM);
    k_cvt_w<<<dim3(KVD/32, DM/32), 256>>>(wv, wvt, KVD, DM);
    k_cvt_w<<<dim3(DM/32,  DM/32), 256>>>(wo, wot, DM,  DM);

    // launch 6 (ncu -s 5 capture target): fused QKV projection + RoPE
    k_qkv<<<dim3(24, MROWS/128), 256>>>(xh, wqt, wkt, wvt, bq, bk, bv,
                                        qh, kh, vh, fc, fs);

    k_transpose_v<<<dim3(HD/32, SEQ/32, BSZ*HKV), 256>>>(vh, vt);

    k_scores<<<dim3(SEQ/128, SEQ/128, BSZ*HQ), 256>>>(qh, kh, attn, scale);
    softmax_kernel<<<BSZ * HQ * SEQ, 256>>>(attn);
    k_attnv<<<dim3(SEQ/128, BSZ*HQ), 256>>>(attn, vt, aoh);

    k_proj_o<<<dim3(DM/128, MROWS/128), 256>>>(aoh, wot, outp);
}

// round 6
// speedup vs baseline: 5.0430x; 1.1077x over previous
#include <cuda_runtime.h>
#include <cuda_fp16.h>
#include <math.h>
#include <stdint.h>

#define BSZ 2
#define SEQ 2048
#define DM  2048
#define HQ  16
#define HKV 4
#define HD  128
#define MROWS (BSZ*SEQ)        // 4096
#define KVD (HKV*HD)           // 512
#define NBH (BSZ*HQ)           // 32
#define NTILE (SEQ/128)        // 16

// ---------------- persistent scratch ----------------------------------------
__device__ __half g_xh [(size_t)MROWS*DM];
__device__ __half g_qh [(size_t)MROWS*DM];
__device__ __half g_kh [(size_t)MROWS*KVD];
__device__ __half g_vh [(size_t)MROWS*KVD];
__device__ __half g_vt [(size_t)BSZ*HKV*HD*SEQ];   // [b][hk][d][s]
__device__ __half g_aoh[(size_t)MROWS*DM];
__device__ __half g_wqt[(size_t)DM*DM];            // [N][K]
__device__ __half g_wkt[(size_t)KVD*DM];
__device__ __half g_wvt[(size_t)KVD*DM];
__device__ __half g_wot[(size_t)DM*DM];
__device__ __half g_sh [(size_t)NBH*NTILE*NTILE*128*128];  // fp16 score tiles
__device__ float  g_pm [(size_t)NBH*SEQ*NTILE];    // per-tile row max
__device__ float  g_pl [(size_t)NBH*SEQ*NTILE];    // per-tile row expsum
__device__ float  g_M  [(size_t)NBH*SEQ];          // row max
__device__ float  g_Li [(size_t)NBH*SEQ];          // 1/row sum

// ---------------- helpers ---------------------------------------------------
__device__ __forceinline__ uint32_t pack2(float lo, float hi){
    __half2 h = __floats2half2_rn(lo, hi);
    return *reinterpret_cast<uint32_t*>(&h);
}
__device__ __forceinline__ uint32_t smem_u32(const void* p){
    uint32_t a;
    asm("{ .reg .u64 t; cvta.to.shared.u64 t, %1; cvt.u32.u64 %0, t; }"
        : "=r"(a) : "l"(p));
    return a;
}
__device__ __forceinline__ void cp16(uint32_t dst, const void* src){
    asm volatile("cp.async.cg.shared.global [%0], [%1], 16;"
        :: "r"(dst), "l"(src) : "memory");
}
#define CP_COMMIT() asm volatile("cp.async.commit_group;" ::: "memory")
#define CP_WAIT0()  asm volatile("cp.async.wait_group 0;" ::: "memory")

__device__ __forceinline__ void ldsm_x4(uint32_t* r, uint32_t addr){
    asm volatile("ldmatrix.sync.aligned.m8n8.x4.shared.b16 {%0,%1,%2,%3}, [%4];"
        : "=r"(r[0]), "=r"(r[1]), "=r"(r[2]), "=r"(r[3]) : "r"(addr));
}
__device__ __forceinline__ void ldsm_x2(uint32_t* r, uint32_t addr){
    asm volatile("ldmatrix.sync.aligned.m8n8.x2.shared.b16 {%0,%1}, [%2];"
        : "=r"(r[0]), "=r"(r[1]) : "r"(addr));
}
__device__ __forceinline__ void mma_f16(float* d, const uint32_t* a, const uint32_t* b){
    asm volatile("mma.sync.aligned.m16n8k16.row.col.f32.f16.f16.f32 "
        "{%0,%1,%2,%3}, {%4,%5,%6,%7}, {%8,%9}, {%0,%1,%2,%3};"
        : "+f"(d[0]), "+f"(d[1]), "+f"(d[2]), "+f"(d[3])
        : "r"(a[0]), "r"(a[1]), "r"(a[2]), "r"(a[3]), "r"(b[0]), "r"(b[1]));
}

#define ACC_INIT(acc) \
    _Pragma("unroll") for (int i=0;i<4;i++) \
        _Pragma("unroll") for (int j=0;j<4;j++) \
            _Pragma("unroll") for (int v=0;v<4;v++) acc[i][j][v]=0.f;

// ============ fp16 core: 128x128 tile, D = A[M,K] @ B[N,K]^T ================
// 8 warps (2m x 4n), warp 64x32, kTile 32, cp.async 2-stage, 1 sync/iter.
// CF: 0 -> C half, 1 -> C float.  cosb!=null -> fused RoPE epilogue.
template<int CF>
__device__ __forceinline__ void tc_fp16(
    const __half* __restrict__ A, int lda, const __half* __restrict__ B, int ldb,
    void* Cv, int ldc, const float* __restrict__ bias, float scale, int niter,
    const float* __restrict__ cosb, const float* __restrict__ sinb, int srow)
{
    __shared__ __half As[2][128*40];
    __shared__ __half Bs[2][128*40];
    const int t = threadIdx.x, lane = t & 31, w = t >> 5;
    const int wm = w >> 2, wn = w & 3, gid = lane >> 2, tg = lane & 3;
    const int row = t >> 1, ch = (t & 1) * 16;

    float acc[4][4][4];
    ACC_INIT(acc)

    const __half* Ag = A + (size_t)row * lda + ch;
    const __half* Bg = B + (size_t)row * ldb + ch;
    uint32_t sa[2], sb[2];
    sa[0] = smem_u32(&As[0][row*40 + ch]);
    sa[1] = smem_u32(&As[1][row*40 + ch]);
    sb[0] = smem_u32(&Bs[0][row*40 + ch]);
    sb[1] = smem_u32(&Bs[1][row*40 + ch]);

    uint32_t aAddr[2], bAddr[2];
    #pragma unroll
    for (int s = 0; s < 2; ++s) {
        aAddr[s] = smem_u32(&As[s][0]) +
            (((wm*64 + (lane & 15)) * 40 + ((lane >> 4) << 3)) << 1);
        bAddr[s] = smem_u32(&Bs[s][0]) +
            (((wn*32 + (lane & 7)) * 40 + (((lane >> 3) & 1) << 3)) << 1);
    }

    cp16(sa[0], Ag);      cp16(sa[0] + 16, Ag + 8);
    cp16(sb[0], Bg);      cp16(sb[0] + 16, Bg + 8);
    CP_COMMIT();

    for (int it = 0; it < niter; ++it) {
        const int cur = it & 1;
        CP_WAIT0();
        __syncthreads();
        if (it + 1 < niter) {
            const int nxt = cur ^ 1;
            const __half* a = Ag + (size_t)(it + 1) * 32;
            const __half* b = Bg + (size_t)(it + 1) * 32;
            cp16(sa[nxt], a); cp16(sa[nxt] + 16, a + 8);
            cp16(sb[nxt], b); cp16(sb[nxt] + 16, b + 8);
            CP_COMMIT();
        }
        #pragma unroll
        for (int c = 0; c < 2; ++c) {
            uint32_t af[4][4], bf[4][2];
            #pragma unroll
            for (int mt = 0; mt < 4; ++mt)
                ldsm_x4(af[mt], aAddr[cur] + mt * 1280 + c * 32);
            #pragma unroll
            for (int nt = 0; nt < 4; ++nt)
                ldsm_x2(bf[nt], bAddr[cur] + nt * 640 + c * 32);
            #pragma unroll
            for (int mt = 0; mt < 4; ++mt)
                #pragma unroll
                for (int nt = 0; nt < 4; ++nt)
                    mma_f16(acc[mt][nt], af[mt], bf[nt]);
        }
    }

    #pragma unroll
    for (int mt = 0; mt < 4; ++mt) {
        const int r0 = wm*64 + mt*16 + gid;
        #pragma unroll
        for (int nt = 0; nt < 4; ++nt) {
            const int cn = wn*32 + nt*8 + 2*tg;
            float b0 = 0.f, b1 = 0.f;
            if (bias) { b0 = bias[cn]; b1 = bias[cn+1]; }
            float v00 = acc[mt][nt][0]*scale + b0;
            float v01 = acc[mt][nt][1]*scale + b1;
            float v10 = acc[mt][nt][2]*scale + b0;
            float v11 = acc[mt][nt][3]*scale + b1;
            if (cosb) {
                const int p = cn >> 1;
                const float c0 = cosb[(srow + r0) * 64 + p];
                const float s0 = sinb[(srow + r0) * 64 + p];
                const float c1 = cosb[(srow + r0 + 8) * 64 + p];
                const float s1 = sinb[(srow + r0 + 8) * 64 + p];
                float t0 = v00*c0 - v01*s0, t1 = v00*s0 + v01*c0;
                v00 = t0; v01 = t1;
                t0 = v10*c1 - v11*s1; t1 = v10*s1 + v11*c1;
                v10 = t0; v11 = t1;
            }
            if (CF == 1) {
                float* C = (float*)Cv;
                *(float2*)(C + (size_t)r0*ldc + cn)     = make_float2(v00, v01);
                *(float2*)(C + (size_t)(r0+8)*ldc + cn) = make_float2(v10, v11);
            } else {
                __half* C = (__half*)Cv;
                *(uint32_t*)(C + (size_t)r0*ldc + cn)     = pack2(v00, v01);
                *(uint32_t*)(C + (size_t)(r0+8)*ldc + cn) = pack2(v10, v11);
            }
        }
    }
}

// ---------------- GEMM wrappers ---------------------------------------------
__global__ __launch_bounds__(256) void k_qkv(
    const __half* __restrict__ xh,
    const __half* __restrict__ wqt, const __half* __restrict__ wkt,
    const __half* __restrict__ wvt,
    const float* __restrict__ bq, const float* __restrict__ bk,
    const float* __restrict__ bv,
    __half* __restrict__ qh, __half* __restrict__ kh, __half* __restrict__ vh,
    const float* __restrict__ cosb, const float* __restrict__ sinb)
{
    const int bx = blockIdx.x, by = blockIdx.y;
    const __half* A = xh + (size_t)by * 128 * DM;
    const int srow = (by & 15) * 128;
    if (bx < 16) {
        tc_fp16<0>(A, DM, wqt + (size_t)bx*128*DM, DM,
                   qh + (size_t)by*128*DM + bx*128, DM,
                   bq + bx*128, 1.0f, DM/32, cosb, sinb, srow);
    } else if (bx < 20) {
        const int c = bx - 16;
        tc_fp16<0>(A, DM, wkt + (size_t)c*128*DM, DM,
                   kh + (size_t)by*128*KVD + c*128, KVD,
                   bk + c*128, 1.0f, DM/32, cosb, sinb, srow);
    } else {
        const int c = bx - 20;
        tc_fp16<0>(A, DM, wvt + (size_t)c*128*DM, DM,
                   vh + (size_t)by*128*KVD + c*128, KVD,
                   bv + c*128, 1.0f, DM/32, (const float*)0, (const float*)0, 0);
    }
}

__global__ __launch_bounds__(256) void k_proj_o(
    const __half* __restrict__ X, const __half* __restrict__ Wt,
    float* __restrict__ C)
{
    tc_fp16<1>(X + (size_t)blockIdx.y*128*DM, DM,
               Wt + (size_t)blockIdx.x*128*DM, DM,
               C + (size_t)blockIdx.y*128*DM + blockIdx.x*128, DM,
               (const float*)0, 1.0f, DM/32, (const float*)0, (const float*)0, 0);
}

// ======== scores: S tile fp16 + per-tile row max / expsum partials ==========
__global__ __launch_bounds__(256) void k_scores2(
    const __half* __restrict__ q, const __half* __restrict__ k,
    __half* __restrict__ sh, float* __restrict__ pm, float* __restrict__ pl,
    float scale)
{
    const int bx = blockIdx.x, by = blockIdx.y;
    if (bx > by) return;
    const int bh = blockIdx.z, b = bh >> 4, h = bh & 15, hk = h >> 2;

    __shared__ __half As[2][128*40];
    __shared__ __half Bs[2][128*40];
    __shared__ float sm_m[4][128];
    __shared__ float sm_l[4][128];
    const int t = threadIdx.x, lane = t & 31, w = t >> 5;
    const int wm = w >> 2, wn = w & 3, gid = lane >> 2, tg = lane & 3;
    const int row = t >> 1, ch = (t & 1) * 16;

    float acc[4][4][4];
    ACC_INIT(acc)

    const __half* Ag = q + ((size_t)b*SEQ + by*128 + row) * DM  + h*HD  + ch;
    const __half* Bg = k + ((size_t)b*SEQ + bx*128 + row) * KVD + hk*HD + ch;
    uint32_t sa[2], sb[2];
    sa[0] = smem_u32(&As[0][row*40 + ch]);
    sa[1] = smem_u32(&As[1][row*40 + ch]);
    sb[0] = smem_u32(&Bs[0][row*40 + ch]);
    sb[1] = smem_u32(&Bs[1][row*40 + ch]);
    uint32_t aAddr[2], bAddr[2];
    #pragma unroll
    for (int s = 0; s < 2; ++s) {
        aAddr[s] = smem_u32(&As[s][0]) +
            (((wm*64 + (lane & 15)) * 40 + ((lane >> 4) << 3)) << 1);
        bAddr[s] = smem_u32(&Bs[s][0]) +
            (((wn*32 + (lane & 7)) * 40 + (((lane >> 3) & 1) << 3)) << 1);
    }

    cp16(sa[0], Ag);      cp16(sa[0] + 16, Ag + 8);
    cp16(sb[0], Bg);      cp16(sb[0] + 16, Bg + 8);
    CP_COMMIT();

    for (int it = 0; it < HD/32; ++it) {
        const int cur = it & 1;
        CP_WAIT0();
        __syncthreads();
        if (it + 1 < HD/32) {
            const int nxt = cur ^ 1;
            const __half* a = Ag + (size_t)(it + 1) * 32;
            const __half* b2 = Bg + (size_t)(it + 1) * 32;
            cp16(sa[nxt], a);  cp16(sa[nxt] + 16, a + 8);
            cp16(sb[nxt], b2); cp16(sb[nxt] + 16, b2 + 8);
            CP_COMMIT();
        }
        #pragma unroll
        for (int c = 0; c < 2; ++c) {
            uint32_t af[4][4], bf[4][2];
            #pragma unroll
            for (int mt = 0; mt < 4; ++mt)
                ldsm_x4(af[mt], aAddr[cur] + mt * 1280 + c * 32);
            #pragma unroll
            for (int nt = 0; nt < 4; ++nt)
                ldsm_x2(bf[nt], bAddr[cur] + nt * 640 + c * 32);
            #pragma unroll
            for (int mt = 0; mt < 4; ++mt)
                #pragma unroll
                for (int nt = 0; nt < 4; ++nt)
                    mma_f16(acc[mt][nt], af[mt], bf[nt]);
        }
    }

    // epilogue: scale, store fp16 tile, row max / expsum partials
    const bool diag = (bx == by);
    __half* tile = sh + (((size_t)bh*NTILE + by)*NTILE + bx) * (128*128);

    #pragma unroll
    for (int mt = 0; mt < 4; ++mt) {
        #pragma unroll
        for (int hv = 0; hv < 2; ++hv) {
            const int r = wm*64 + mt*16 + gid + hv*8;
            float vals[8];
            #pragma unroll
            for (int nt = 0; nt < 4; ++nt) {
                vals[nt*2]   = acc[mt][nt][hv*2]   * scale;
                vals[nt*2+1] = acc[mt][nt][hv*2+1] * scale;
                const int cn = wn*32 + nt*8 + 2*tg;
                *(uint32_t*)(tile + (size_t)r*128 + cn) =
                    pack2(vals[nt*2], vals[nt*2+1]);
            }
            if (diag) {
                #pragma unroll
                for (int nt = 0; nt < 4; ++nt) {
                    const int cn = wn*32 + nt*8 + 2*tg;
                    if (cn     > r) vals[nt*2]   = -1e30f;
                    if (cn + 1 > r) vals[nt*2+1] = -1e30f;
                }
            }
            float m = -1e30f;
            #pragma unroll
            for (int i = 0; i < 8; ++i) m = fmaxf(m, vals[i]);
            m = fmaxf(m, __shfl_xor_sync(0xFFFFFFFFu, m, 1));
            m = fmaxf(m, __shfl_xor_sync(0xFFFFFFFFu, m, 2));
            float l = 0.f;
            #pragma unroll
            for (int i = 0; i < 8; ++i)
                if (vals[i] > -1e29f) l += __expf(vals[i] - m);
            l += __shfl_xor_sync(0xFFFFFFFFu, l, 1);
            l += __shfl_xor_sync(0xFFFFFFFFu, l, 2);
            if (tg == 0) { sm_m[wn][r] = m; sm_l[wn][r] = l; }
        }
    }
    __syncthreads();
    if (t < 128) {
        float M = -1e30f;
        #pragma unroll
        for (int w2 = 0; w2 < 4; ++w2) M = fmaxf(M, sm_m[w2][t]);
        float L = 0.f;
        #pragma unroll
        for (int w2 = 0; w2 < 4; ++w2)
            if (sm_m[w2][t] > -1e29f) L += sm_l[w2][t] * __expf(sm_m[w2][t] - M);
        const size_t ridx = ((size_t)bh*SEQ + by*128 + t) * NTILE + bx;
        pm[ridx] = M; pl[ridx] = L;
    }
}

// ======== reduce: per-row global max and 1/sum ==============================
__global__ void k_reduce(const float* __restrict__ pm, const float* __restrict__ pl,
                         float* __restrict__ Mv, float* __restrict__ Li)
{
    const int idx = blockIdx.x * blockDim.x + threadIdx.x;  // bh*SEQ + i
    if (idx >= NBH*SEQ) return;
    const int i = idx & (SEQ - 1);
    const int nt = (i >> 7) + 1;
    const float* pmr = pm + (size_t)idx * NTILE;
    const float* plr = pl + (size_t)idx * NTILE;
    float M = -1e30f;
    for (int t2 = 0; t2 < nt; ++t2) M = fmaxf(M, pmr[t2]);
    float L = 0.f;
    for (int t2 = 0; t2 < nt; ++t2)
        if (pmr[t2] > -1e29f) L += plr[t2] * __expf(pmr[t2] - M);
    Mv[idx] = M;
    Li[idx] = 1.0f / L;
}

// ======== zero-fill strictly-upper attn tiles ===============================
__global__ __launch_bounds__(256) void k_zero_upper(float* __restrict__ attn)
{
    const int bx = blockIdx.x, by = blockIdx.y;
    if (bx <= by) return;
    const int bh = blockIdx.z;
    float* base = attn + ((size_t)bh*SEQ + by*128)*SEQ + bx*128;
    const float4 z = make_float4(0.f, 0.f, 0.f, 0.f);
    for (int f = threadIdx.x; f < 128*32; f += 256) {
        const int r = f >> 5, c4 = f & 31;
        *(float4*)(base + (size_t)r*SEQ + c4*4) = z;
    }
}

// ======== fused normalize + P write + P@V ===================================
__global__ __launch_bounds__(256) void k_pv(
    const __half* __restrict__ sh, const float* __restrict__ Mv,
    const float* __restrict__ Li, const __half* __restrict__ vt,
    float* __restrict__ attn, __half* __restrict__ ao)
{
    const int by = blockIdx.x, bh = blockIdx.y;
    const int b = bh >> 4, h = bh & 15, hk = h >> 2;
    const int i0 = by * 128;

    __shared__ __half As[128*40];
    __shared__ __half Bs[128*40];
    const int t = threadIdx.x, lane = t & 31, w = t >> 5;
    const int wm = w >> 2, wn = w & 3, gid = lane >> 2, tg = lane & 3;
    const int row = t >> 1, ch = (t & 1) * 16;

    float acc[4][4][4];
    ACC_INIT(acc)

    const float Mrow = Mv[(size_t)bh*SEQ + i0 + row];
    const float invL = Li[(size_t)bh*SEQ + i0 + row];
    const __half* shb = sh + ((size_t)bh*NTILE + by)*NTILE*(128*128);
    const __half* vtp = vt + (size_t)(b*HKV + hk)*HD*SEQ + (size_t)row*SEQ + ch;
    float* arow = attn + ((size_t)bh*SEQ + i0 + row)*SEQ;

    const uint32_t aAddr = smem_u32(As) +
        (((wm*64 + (lane & 15)) * 40 + ((lane >> 4) << 3)) << 1);
    const uint32_t bAddr = smem_u32(Bs) +
        (((wn*32 + (lane & 7)) * 40 + (((lane >> 3) & 1) << 3)) << 1);

    const int njc = (by + 1) * 4;                  // 32-wide j chunks
    for (int jc = 0; jc < njc; ++jc) {
        const int tj = jc >> 2, jin = (jc & 3) * 32;
        const __half* sp = shb + (size_t)tj*(128*128) + (size_t)row*128 + jin + ch;
        uint4 sv0 = *(const uint4*)sp;
        uint4 sv1 = *(const uint4*)(sp + 8);

        float p[16];
        {
            const __half2* h2 = (const __half2*)&sv0;
            #pragma unroll
            for (int g = 0; g < 4; ++g) {
                float2 f = __half22float2(h2[g]);
                p[g*2]   = __expf(f.x - Mrow) * invL;
                p[g*2+1] = __expf(f.y - Mrow) * invL;
            }
            const __half2* h3 = (const __half2*)&sv1;
            #pragma unroll
            for (int g = 0; g < 4; ++g) {
                float2 f = __half22float2(h3[g]);
                p[8+g*2]   = __expf(f.x - Mrow) * invL;
                p[8+g*2+1] = __expf(f.y - Mrow) * invL;
            }
        }
        if (tj == by) {
            #pragma unroll
            for (int kk = 0; kk < 16; ++kk)
                if (jin + ch + kk > row) p[kk] = 0.f;
        }
        // write normalized P (fp32) to attn
        float* ap = arow + tj*128 + jin + ch;
        *(float4*)(ap)      = make_float4(p[0],  p[1],  p[2],  p[3]);
        *(float4*)(ap + 4)  = make_float4(p[4],  p[5],  p[6],  p[7]);
        *(float4*)(ap + 8)  = make_float4(p[8],  p[9],  p[10], p[11]);
        *(float4*)(ap + 12) = make_float4(p[12], p[13], p[14], p[15]);

        // P fp16 to smem
        uint4* aw = (uint4*)&As[row*40 + ch];
        aw[0] = make_uint4(pack2(p[0],p[1]),  pack2(p[2],p[3]),
                           pack2(p[4],p[5]),  pack2(p[6],p[7]));
        aw[1] = make_uint4(pack2(p[8],p[9]),  pack2(p[10],p[11]),
                           pack2(p[12],p[13]),pack2(p[14],p[15]));
        // V^T chunk [d=row][j]
        const __half* vp = vtp + jc*32;
        uint4* bw = (uint4*)&Bs[row*40 + ch];
        bw[0] = *(const uint4*)vp;
        bw[1] = *(const uint4*)(vp + 8);
        __syncthreads();

        #pragma unroll
        for (int c = 0; c < 2; ++c) {
            uint32_t af[4][4], bf[4][2];
            #pragma unroll
            for (int mt = 0; mt < 4; ++mt)
                ldsm_x4(af[mt], aAddr + mt * 1280 + c * 32);
            #pragma unroll
            for (int nt = 0; nt < 4; ++nt)
                ldsm_x2(bf[nt], bAddr + nt * 640 + c * 32);
            #pragma unroll
            for (int mt = 0; mt < 4; ++mt)
                #pragma unroll
                for (int nt = 0; nt < 4; ++nt)
                    mma_f16(acc[mt][nt], af[mt], bf[nt]);
        }
        __syncthreads();
    }

    #pragma unroll
    for (int mt = 0; mt < 4; ++mt) {
        const int r0 = wm*64 + mt*16 + gid;
        #pragma unroll
        for (int nt = 0; nt < 4; ++nt) {
            const int cn = wn*32 + nt*8 + 2*tg;
            __half* C = ao + ((size_t)b*SEQ + i0)*DM + h*HD;
            *(uint32_t*)(C + (size_t)r0*DM + cn) =
                pack2(acc[mt][nt][0], acc[mt][nt][1]);
            *(uint32_t*)(C + (size_t)(r0+8)*DM + cn) =
                pack2(acc[mt][nt][2], acc[mt][nt][3]);
        }
    }
}

// ---------------- converts / transposes -------------------------------------
__global__ void k_cvt_x(const float* __restrict__ x, __half* __restrict__ xh, int n4)
{
    int i = blockIdx.x * blockDim.x + threadIdx.x;
    if (i >= n4) return;
    float4 v = ((const float4*)x)[i];
    ((uint2*)xh)[i] = make_uint2(pack2(v.x, v.y), pack2(v.z, v.w));
}

__global__ __launch_bounds__(256) void k_cvt_w(
    const float* __restrict__ src, __half* __restrict__ dst, int N, int K)
{
    __shared__ float tile[32][33];
    const int tx = threadIdx.x & 31, ty = threadIdx.x >> 5;
    const int r0 = blockIdx.y * 32, c0 = blockIdx.x * 32;
    #pragma unroll
    for (int i = 0; i < 32; i += 8)
        tile[ty + i][tx] = src[(size_t)(r0 + ty + i) * N + c0 + tx];
    __syncthreads();
    #pragma unroll
    for (int i = 0; i < 32; i += 8)
        dst[(size_t)(c0 + ty + i) * K + r0 + tx] = __float2half(tile[tx][ty + i]);
}

__global__ __launch_bounds__(256) void k_transpose_v(
    const __half* __restrict__ v, __half* __restrict__ vt)
{
    __shared__ __half tile[32][33];
    const int z = blockIdx.z, b = z >> 2, hk = z & 3;
    const int tx = threadIdx.x & 31, ty = threadIdx.x >> 5;
    const int r0 = blockIdx.y * 32, c0 = blockIdx.x * 32;
    #pragma unroll
    for (int i = 0; i < 32; i += 8)
        tile[ty + i][tx] = v[((size_t)b*SEQ + r0 + ty + i) * KVD + hk*HD + c0 + tx];
    __syncthreads();
    #pragma unroll
    for (int i = 0; i < 32; i += 8)
        vt[((size_t)(b*HKV + hk)*HD + c0 + ty + i) * SEQ + r0 + tx] = tile[tx][ty + i];
}

// ---------------- launch ------------------------------------------------------
extern "C" void kernel_launch(void* const* d_in, const int* in_sizes, int n_in,
                              void* d_out, int out_size)
{
    const float* x  = (const float*)d_in[0];
    const float* fc = (const float*)d_in[1];
    const float* fs = (const float*)d_in[2];
    const float* wq = (const float*)d_in[3];
    const float* bq = (const float*)d_in[4];
    const float* wk = (const float*)d_in[5];
    const float* bk = (const float*)d_in[6];
    const float* wv = (const float*)d_in[7];
    const float* bv = (const float*)d_in[8];
    const float* wo = (const float*)d_in[9];

    float* outp = (float*)d_out;
    float* attn = outp + (size_t)BSZ * SEQ * DM;

    __half *xh, *qh, *kh, *vh, *vt, *aoh, *wqt, *wkt, *wvt, *wot, *sh;
    float *pm, *pl, *Mv, *Li;
    cudaGetSymbolAddress((void**)&xh,  g_xh);
    cudaGetSymbolAddress((void**)&qh,  g_qh);
    cudaGetSymbolAddress((void**)&kh,  g_kh);
    cudaGetSymbolAddress((void**)&vh,  g_vh);
    cudaGetSymbolAddress((void**)&vt,  g_vt);
    cudaGetSymbolAddress((void**)&aoh, g_aoh);
    cudaGetSymbolAddress((void**)&wqt, g_wqt);
    cudaGetSymbolAddress((void**)&wkt, g_wkt);
    cudaGetSymbolAddress((void**)&wvt, g_wvt);
    cudaGetSymbolAddress((void**)&wot, g_wot);
    cudaGetSymbolAddress((void**)&sh,  g_sh);
    cudaGetSymbolAddress((void**)&pm,  g_pm);
    cudaGetSymbolAddress((void**)&pl,  g_pl);
    cudaGetSymbolAddress((void**)&Mv,  g_M);
    cudaGetSymbolAddress((void**)&Li,  g_Li);

    const float scale = 1.0f / sqrtf((float)DM);

    // conversions (launches 1-5)
    k_cvt_x<<<(MROWS*DM/4 + 255)/256, 256>>>(x, xh, MROWS*DM/4);
    k_cvt_w<<<dim3(DM/32,  DM/32), 256>>>(wq, wqt, DM,  DM);
    k_cvt_w<<<dim3(KVD/32, DM/32), 256>>>(wk, wkt, KVD, DM);
    k_cvt_w<<<dim3(KVD/32, DM/32), 256>>>(wv, wvt, KVD, DM);
    k_cvt_w<<<dim3(DM/32,  DM/32), 256>>>(wo, wot, DM,  DM);

    // launch 6 (ncu target): fused QKV projection + RoPE
    k_qkv<<<dim3(24, MROWS/128), 256>>>(xh, wqt, wkt, wvt, bq, bk, bv,
                                        qh, kh, vh, fc, fs);

    k_transpose_v<<<dim3(HD/32, SEQ/32, BSZ*HKV), 256>>>(vh, vt);
    k_zero_upper<<<dim3(NTILE, NTILE, NBH), 256>>>(attn);

    k_scores2<<<dim3(NTILE, NTILE, NBH), 256>>>(qh, kh, sh, pm, pl, scale);
    k_reduce<<<(NBH*SEQ + 255)/256, 256>>>(pm, pl, Mv, Li);
    k_pv<<<dim3(NTILE, NBH), 256>>>(sh, Mv, Li, vt, attn, aoh);

    k_proj_o<<<dim3(DM/128, MROWS/128), 256>>>(aoh, wot, outp);
}

// round 7
// speedup vs baseline: 5.0980x; 1.0109x over previous
#include <cuda_runtime.h>
#include <cuda_fp16.h>
#include <math.h>
#include <stdint.h>

#define BSZ 2
#define SEQ 2048
#define DM  2048
#define HQ  16
#define HKV 4
#define HD  128
#define MROWS (BSZ*SEQ)        // 4096
#define KVD (HKV*HD)           // 512
#define NBH (BSZ*HQ)           // 32
#define NTILE (SEQ/128)        // 16

// ---------------- persistent scratch ----------------------------------------
__device__ __half g_xh [(size_t)MROWS*DM];
__device__ __half g_qh [(size_t)MROWS*DM];
__device__ __half g_kh [(size_t)MROWS*KVD];
__device__ __half g_vh [(size_t)MROWS*KVD];
__device__ __half g_vt [(size_t)BSZ*HKV*HD*SEQ];   // [b][hk][d][s]
__device__ __half g_aoh[(size_t)MROWS*DM];
__device__ __half g_wqt[(size_t)DM*DM];            // [N][K]
__device__ __half g_wkt[(size_t)KVD*DM];
__device__ __half g_wvt[(size_t)KVD*DM];
__device__ __half g_wot[(size_t)DM*DM];
__device__ __half g_sh [(size_t)NBH*NTILE*NTILE*128*128];  // fp16 score tiles
__device__ float  g_pm [(size_t)NBH*SEQ*NTILE];    // per-tile row max
__device__ float  g_pl [(size_t)NBH*SEQ*NTILE];    // per-tile row expsum
__device__ float  g_M  [(size_t)NBH*SEQ];          // row max
__device__ float  g_Li [(size_t)NBH*SEQ];          // 1/row sum

// ---------------- helpers ---------------------------------------------------
__device__ __forceinline__ uint32_t pack2(float lo, float hi){
    __half2 h = __floats2half2_rn(lo, hi);
    return *reinterpret_cast<uint32_t*>(&h);
}
__device__ __forceinline__ uint32_t smem_u32(const void* p){
    uint32_t a;
    asm("{ .reg .u64 t; cvta.to.shared.u64 t, %1; cvt.u32.u64 %0, t; }"
        : "=r"(a) : "l"(p));
    return a;
}
__device__ __forceinline__ void cp16(uint32_t dst, const void* src){
    asm volatile("cp.async.cg.shared.global [%0], [%1], 16;"
        :: "r"(dst), "l"(src) : "memory");
}
#define CP_COMMIT() asm volatile("cp.async.commit_group;" ::: "memory")
#define CP_WAIT0()  asm volatile("cp.async.wait_group 0;" ::: "memory")

__device__ __forceinline__ void ldsm_x4(uint32_t* r, uint32_t addr){
    asm volatile("ldmatrix.sync.aligned.m8n8.x4.shared.b16 {%0,%1,%2,%3}, [%4];"
        : "=r"(r[0]), "=r"(r[1]), "=r"(r[2]), "=r"(r[3]) : "r"(addr));
}
__device__ __forceinline__ void ldsm_x2(uint32_t* r, uint32_t addr){
    asm volatile("ldmatrix.sync.aligned.m8n8.x2.shared.b16 {%0,%1}, [%2];"
        : "=r"(r[0]), "=r"(r[1]) : "r"(addr));
}
__device__ __forceinline__ void mma_f16(float* d, const uint32_t* a, const uint32_t* b){
    asm volatile("mma.sync.aligned.m16n8k16.row.col.f32.f16.f16.f32 "
        "{%0,%1,%2,%3}, {%4,%5,%6,%7}, {%8,%9}, {%0,%1,%2,%3};"
        : "+f"(d[0]), "+f"(d[1]), "+f"(d[2]), "+f"(d[3])
        : "r"(a[0]), "r"(a[1]), "r"(a[2]), "r"(a[3]), "r"(b[0]), "r"(b[1]));
}

#define ACC_INIT(acc) \
    _Pragma("unroll") for (int i=0;i<4;i++) \
        _Pragma("unroll") for (int j=0;j<4;j++) \
            _Pragma("unroll") for (int v=0;v<4;v++) acc[i][j][v]=0.f;

// ============ fp16 core: 128x128 tile, D = A[M,K] @ B[N,K]^T ================
template<int CF>
__device__ __forceinline__ void tc_fp16(
    const __half* __restrict__ A, int lda, const __half* __restrict__ B, int ldb,
    void* Cv, int ldc, const float* __restrict__ bias, float scale, int niter,
    const float* __restrict__ cosb, const float* __restrict__ sinb, int srow)
{
    __shared__ __half As[2][128*40];
    __shared__ __half Bs[2][128*40];
    const int t = threadIdx.x, lane = t & 31, w = t >> 5;
    const int wm = w >> 2, wn = w & 3, gid = lane >> 2, tg = lane & 3;
    const int row = t >> 1, ch = (t & 1) * 16;

    float acc[4][4][4];
    ACC_INIT(acc)

    const __half* Ag = A + (size_t)row * lda + ch;
    const __half* Bg = B + (size_t)row * ldb + ch;
    uint32_t sa[2], sb[2];
    sa[0] = smem_u32(&As[0][row*40 + ch]);
    sa[1] = smem_u32(&As[1][row*40 + ch]);
    sb[0] = smem_u32(&Bs[0][row*40 + ch]);
    sb[1] = smem_u32(&Bs[1][row*40 + ch]);

    uint32_t aAddr[2], bAddr[2];
    #pragma unroll
    for (int s = 0; s < 2; ++s) {
        aAddr[s] = smem_u32(&As[s][0]) +
            (((wm*64 + (lane & 15)) * 40 + ((lane >> 4) << 3)) << 1);
        bAddr[s] = smem_u32(&Bs[s][0]) +
            (((wn*32 + (lane & 7)) * 40 + (((lane >> 3) & 1) << 3)) << 1);
    }

    cp16(sa[0], Ag);      cp16(sa[0] + 16, Ag + 8);
    cp16(sb[0], Bg);      cp16(sb[0] + 16, Bg + 8);
    CP_COMMIT();

    for (int it = 0; it < niter; ++it) {
        const int cur = it & 1;
        CP_WAIT0();
        __syncthreads();
        if (it + 1 < niter) {
            const int nxt = cur ^ 1;
            const __half* a = Ag + (size_t)(it + 1) * 32;
            const __half* b = Bg + (size_t)(it + 1) * 32;
            cp16(sa[nxt], a); cp16(sa[nxt] + 16, a + 8);
            cp16(sb[nxt], b); cp16(sb[nxt] + 16, b + 8);
            CP_COMMIT();
        }
        #pragma unroll
        for (int c = 0; c < 2; ++c) {
            uint32_t af[4][4], bf[4][2];
            #pragma unroll
            for (int mt = 0; mt < 4; ++mt)
                ldsm_x4(af[mt], aAddr[cur] + mt * 1280 + c * 32);
            #pragma unroll
            for (int nt = 0; nt < 4; ++nt)
                ldsm_x2(bf[nt], bAddr[cur] + nt * 640 + c * 32);
            #pragma unroll
            for (int mt = 0; mt < 4; ++mt)
                #pragma unroll
                for (int nt = 0; nt < 4; ++nt)
                    mma_f16(acc[mt][nt], af[mt], bf[nt]);
        }
    }

    #pragma unroll
    for (int mt = 0; mt < 4; ++mt) {
        const int r0 = wm*64 + mt*16 + gid;
        #pragma unroll
        for (int nt = 0; nt < 4; ++nt) {
            const int cn = wn*32 + nt*8 + 2*tg;
            float b0 = 0.f, b1 = 0.f;
            if (bias) { b0 = bias[cn]; b1 = bias[cn+1]; }
            float v00 = acc[mt][nt][0]*scale + b0;
            float v01 = acc[mt][nt][1]*scale + b1;
            float v10 = acc[mt][nt][2]*scale + b0;
            float v11 = acc[mt][nt][3]*scale + b1;
            if (cosb) {
                const int p = cn >> 1;
                const float c0 = cosb[(srow + r0) * 64 + p];
                const float s0 = sinb[(srow + r0) * 64 + p];
                const float c1 = cosb[(srow + r0 + 8) * 64 + p];
                const float s1 = sinb[(srow + r0 + 8) * 64 + p];
                float t0 = v00*c0 - v01*s0, t1 = v00*s0 + v01*c0;
                v00 = t0; v01 = t1;
                t0 = v10*c1 - v11*s1; t1 = v10*s1 + v11*c1;
                v10 = t0; v11 = t1;
            }
            if (CF == 1) {
                float* C = (float*)Cv;
                *(float2*)(C + (size_t)r0*ldc + cn)     = make_float2(v00, v01);
                *(float2*)(C + (size_t)(r0+8)*ldc + cn) = make_float2(v10, v11);
            } else {
                __half* C = (__half*)Cv;
                *(uint32_t*)(C + (size_t)r0*ldc + cn)     = pack2(v00, v01);
                *(uint32_t*)(C + (size_t)(r0+8)*ldc + cn) = pack2(v10, v11);
            }
        }
    }
}

// ---------------- GEMM wrappers ---------------------------------------------
__global__ __launch_bounds__(256) void k_qkv(
    const __half* __restrict__ xh,
    const __half* __restrict__ wqt, const __half* __restrict__ wkt,
    const __half* __restrict__ wvt,
    const float* __restrict__ bq, const float* __restrict__ bk,
    const float* __restrict__ bv,
    __half* __restrict__ qh, __half* __restrict__ kh, __half* __restrict__ vh,
    const float* __restrict__ cosb, const float* __restrict__ sinb)
{
    const int bx = blockIdx.x, by = blockIdx.y;
    const __half* A = xh + (size_t)by * 128 * DM;
    const int srow = (by & 15) * 128;
    if (bx < 16) {
        tc_fp16<0>(A, DM, wqt + (size_t)bx*128*DM, DM,
                   qh + (size_t)by*128*DM + bx*128, DM,
                   bq + bx*128, 1.0f, DM/32, cosb, sinb, srow);
    } else if (bx < 20) {
        const int c = bx - 16;
        tc_fp16<0>(A, DM, wkt + (size_t)c*128*DM, DM,
                   kh + (size_t)by*128*KVD + c*128, KVD,
                   bk + c*128, 1.0f, DM/32, cosb, sinb, srow);
    } else {
        const int c = bx - 20;
        tc_fp16<0>(A, DM, wvt + (size_t)c*128*DM, DM,
                   vh + (size_t)by*128*KVD + c*128, KVD,
                   bv + c*128, 1.0f, DM/32, (const float*)0, (const float*)0, 0);
    }
}

__global__ __launch_bounds__(256) void k_proj_o(
    const __half* __restrict__ X, const __half* __restrict__ Wt,
    float* __restrict__ C)
{
    tc_fp16<1>(X + (size_t)blockIdx.y*128*DM, DM,
               Wt + (size_t)blockIdx.x*128*DM, DM,
               C + (size_t)blockIdx.y*128*DM + blockIdx.x*128, DM,
               (const float*)0, 1.0f, DM/32, (const float*)0, (const float*)0, 0);
}

// ======== scores: S tile fp16 + partials; upper tiles zero-fill attn ========
__global__ __launch_bounds__(256) void k_scores2(
    const __half* __restrict__ q, const __half* __restrict__ k,
    __half* __restrict__ sh, float* __restrict__ pm, float* __restrict__ pl,
    float* __restrict__ attn, float scale)
{
    const int bx = blockIdx.x, by = blockIdx.y;
    const int bh = blockIdx.z, b = bh >> 4, h = bh & 15, hk = h >> 2;

    if (bx > by) {   // strictly-upper tile: zero-fill the attn output here
        float* base = attn + ((size_t)bh*SEQ + by*128)*SEQ + bx*128;
        const float4 z = make_float4(0.f, 0.f, 0.f, 0.f);
        for (int f = threadIdx.x; f < 128*32; f += 256) {
            const int r = f >> 5, c4 = f & 31;
            *(float4*)(base + (size_t)r*SEQ + c4*4) = z;
        }
        return;
    }

    __shared__ __half As[2][128*40];
    __shared__ __half Bs[2][128*40];
    __shared__ float sm_m[4][128];
    __shared__ float sm_l[4][128];
    const int t = threadIdx.x, lane = t & 31, w = t >> 5;
    const int wm = w >> 2, wn = w & 3, gid = lane >> 2, tg = lane & 3;
    const int row = t >> 1, ch = (t & 1) * 16;

    float acc[4][4][4];
    ACC_INIT(acc)

    const __half* Ag = q + ((size_t)b*SEQ + by*128 + row) * DM  + h*HD  + ch;
    const __half* Bg = k + ((size_t)b*SEQ + bx*128 + row) * KVD + hk*HD + ch;
    uint32_t sa[2], sb[2];
    sa[0] = smem_u32(&As[0][row*40 + ch]);
    sa[1] = smem_u32(&As[1][row*40 + ch]);
    sb[0] = smem_u32(&Bs[0][row*40 + ch]);
    sb[1] = smem_u32(&Bs[1][row*40 + ch]);
    uint32_t aAddr[2], bAddr[2];
    #pragma unroll
    for (int s = 0; s < 2; ++s) {
        aAddr[s] = smem_u32(&As[s][0]) +
            (((wm*64 + (lane & 15)) * 40 + ((lane >> 4) << 3)) << 1);
        bAddr[s] = smem_u32(&Bs[s][0]) +
            (((wn*32 + (lane & 7)) * 40 + (((lane >> 3) & 1) << 3)) << 1);
    }

    cp16(sa[0], Ag);      cp16(sa[0] + 16, Ag + 8);
    cp16(sb[0], Bg);      cp16(sb[0] + 16, Bg + 8);
    CP_COMMIT();

    for (int it = 0; it < HD/32; ++it) {
        const int cur = it & 1;
        CP_WAIT0();
        __syncthreads();
        if (it + 1 < HD/32) {
            const int nxt = cur ^ 1;
            const __half* a = Ag + (size_t)(it + 1) * 32;
            const __half* b2 = Bg + (size_t)(it + 1) * 32;
            cp16(sa[nxt], a);  cp16(sa[nxt] + 16, a + 8);
            cp16(sb[nxt], b2); cp16(sb[nxt] + 16, b2 + 8);
            CP_COMMIT();
        }
        #pragma unroll
        for (int c = 0; c < 2; ++c) {
            uint32_t af[4][4], bf[4][2];
            #pragma unroll
            for (int mt = 0; mt < 4; ++mt)
                ldsm_x4(af[mt], aAddr[cur] + mt * 1280 + c * 32);
            #pragma unroll
            for (int nt = 0; nt < 4; ++nt)
                ldsm_x2(bf[nt], bAddr[cur] + nt * 640 + c * 32);
            #pragma unroll
            for (int mt = 0; mt < 4; ++mt)
                #pragma unroll
                for (int nt = 0; nt < 4; ++nt)
                    mma_f16(acc[mt][nt], af[mt], bf[nt]);
        }
    }

    const bool diag = (bx == by);
    __half* tile = sh + (((size_t)bh*NTILE + by)*NTILE + bx) * (128*128);

    #pragma unroll
    for (int mt = 0; mt < 4; ++mt) {
        #pragma unroll
        for (int hv = 0; hv < 2; ++hv) {
            const int r = wm*64 + mt*16 + gid + hv*8;
            float vals[8];
            #pragma unroll
            for (int nt = 0; nt < 4; ++nt) {
                vals[nt*2]   = acc[mt][nt][hv*2]   * scale;
                vals[nt*2+1] = acc[mt][nt][hv*2+1] * scale;
                const int cn = wn*32 + nt*8 + 2*tg;
                *(uint32_t*)(tile + (size_t)r*128 + cn) =
                    pack2(vals[nt*2], vals[nt*2+1]);
            }
            if (diag) {
                #pragma unroll
                for (int nt = 0; nt < 4; ++nt) {
                    const int cn = wn*32 + nt*8 + 2*tg;
                    if (cn     > r) vals[nt*2]   = -1e30f;
                    if (cn + 1 > r) vals[nt*2+1] = -1e30f;
                }
            }
            float m = -1e30f;
            #pragma unroll
            for (int i = 0; i < 8; ++i) m = fmaxf(m, vals[i]);
            m = fmaxf(m, __shfl_xor_sync(0xFFFFFFFFu, m, 1));
            m = fmaxf(m, __shfl_xor_sync(0xFFFFFFFFu, m, 2));
            float l = 0.f;
            #pragma unroll
            for (int i = 0; i < 8; ++i)
                if (vals[i] > -1e29f) l += __expf(vals[i] - m);
            l += __shfl_xor_sync(0xFFFFFFFFu, l, 1);
            l += __shfl_xor_sync(0xFFFFFFFFu, l, 2);
            if (tg == 0) { sm_m[wn][r] = m; sm_l[wn][r] = l; }
        }
    }
    __syncthreads();
    if (t < 128) {
        float M = -1e30f;
        #pragma unroll
        for (int w2 = 0; w2 < 4; ++w2) M = fmaxf(M, sm_m[w2][t]);
        float L = 0.f;
        #pragma unroll
        for (int w2 = 0; w2 < 4; ++w2)
            if (sm_m[w2][t] > -1e29f) L += sm_l[w2][t] * __expf(sm_m[w2][t] - M);
        const size_t ridx = ((size_t)bh*SEQ + by*128 + t) * NTILE + bx;
        pm[ridx] = M; pl[ridx] = L;
    }
}

// ======== reduce: per-row global max and 1/sum ==============================
__global__ void k_reduce(const float* __restrict__ pm, const float* __restrict__ pl,
                         float* __restrict__ Mv, float* __restrict__ Li)
{
    const int idx = blockIdx.x * blockDim.x + threadIdx.x;
    if (idx >= NBH*SEQ) return;
    const int i = idx & (SEQ - 1);
    const int nt = (i >> 7) + 1;
    const float* pmr = pm + (size_t)idx * NTILE;
    const float* plr = pl + (size_t)idx * NTILE;
    float M = -1e30f;
    for (int t2 = 0; t2 < nt; ++t2) M = fmaxf(M, pmr[t2]);
    float L = 0.f;
    for (int t2 = 0; t2 < nt; ++t2)
        if (pmr[t2] > -1e29f) L += plr[t2] * __expf(pmr[t2] - M);
    Mv[idx] = M;
    Li[idx] = 1.0f / L;
}

// ======== fused normalize + P write + P@V (register-prefetched) =============
__global__ __launch_bounds__(256) void k_pv(
    const __half* __restrict__ sh, const float* __restrict__ Mv,
    const float* __restrict__ Li, const __half* __restrict__ vt,
    float* __restrict__ attn, __half* __restrict__ ao)
{
    const int by = NTILE - 1 - blockIdx.x;       // big tiles first
    const int bh = blockIdx.y;
    const int b = bh >> 4, h = bh & 15, hk = h >> 2;
    const int i0 = by * 128;

    __shared__ __half As[128*40];
    __shared__ __half Bs[128*40];
    const int t = threadIdx.x, lane = t & 31, w = t >> 5;
    const int wm = w >> 2, wn = w & 3, gid = lane >> 2, tg = lane & 3;
    const int row = t >> 1, ch = (t & 1) * 16;

    float acc[4][4][4];
    ACC_INIT(acc)

    const float Mrow = Mv[(size_t)bh*SEQ + i0 + row];
    const float invL = Li[(size_t)bh*SEQ + i0 + row];
    const __half* shb = sh + ((size_t)bh*NTILE + by)*NTILE*(128*128);
    const __half* vtp = vt + (size_t)(b*HKV + hk)*HD*SEQ + (size_t)row*SEQ + ch;
    float* arow = attn + ((size_t)bh*SEQ + i0 + row)*SEQ;

    const uint32_t aAddr = smem_u32(As) +
        (((wm*64 + (lane & 15)) * 40 + ((lane >> 4) << 3)) << 1);
    const uint32_t bAddr = smem_u32(Bs) +
        (((wn*32 + (lane & 7)) * 40 + (((lane >> 3) & 1) << 3)) << 1);

    const int njc = (by + 1) * 4;                  // 32-wide j chunks

    auto sptr = [&](int jc) -> const __half* {
        const int tj = jc >> 2, jin = (jc & 3) * 32;
        return shb + (size_t)tj*(128*128) + (size_t)row*128 + jin + ch;
    };

    uint4 sv0, sv1, vv0, vv1;
    {
        const __half* sp = sptr(0);
        sv0 = *(const uint4*)sp;  sv1 = *(const uint4*)(sp + 8);
        vv0 = *(const uint4*)vtp; vv1 = *(const uint4*)(vtp + 8);
    }

    for (int jc = 0; jc < njc; ++jc) {
        const int tj = jc >> 2, jin = (jc & 3) * 32;

        float p[16];
        {
            const __half2* h2 = (const __half2*)&sv0;
            #pragma unroll
            for (int g = 0; g < 4; ++g) {
                float2 f = __half22float2(h2[g]);
                p[g*2]   = __expf(f.x - Mrow) * invL;
                p[g*2+1] = __expf(f.y - Mrow) * invL;
            }
            const __half2* h3 = (const __half2*)&sv1;
            #pragma unroll
            for (int g = 0; g < 4; ++g) {
                float2 f = __half22float2(h3[g]);
                p[8+g*2]   = __expf(f.x - Mrow) * invL;
                p[8+g*2+1] = __expf(f.y - Mrow) * invL;
            }
        }
        if (tj == by) {
            #pragma unroll
            for (int kk = 0; kk < 16; ++kk)
                if (jin + ch + kk > row) p[kk] = 0.f;
        }
        // write normalized P (fp32) to attn
        float* ap = arow + tj*128 + jin + ch;
        *(float4*)(ap)      = make_float4(p[0],  p[1],  p[2],  p[3]);
        *(float4*)(ap + 4)  = make_float4(p[4],  p[5],  p[6],  p[7]);
        *(float4*)(ap + 8)  = make_float4(p[8],  p[9],  p[10], p[11]);
        *(float4*)(ap + 12) = make_float4(p[12], p[13], p[14], p[15]);

        // P fp16 + V^T chunk to smem
        uint4* aw = (uint4*)&As[row*40 + ch];
        aw[0] = make_uint4(pack2(p[0],p[1]),  pack2(p[2],p[3]),
                           pack2(p[4],p[5]),  pack2(p[6],p[7]));
        aw[1] = make_uint4(pack2(p[8],p[9]),  pack2(p[10],p[11]),
                           pack2(p[12],p[13]),pack2(p[14],p[15]));
        uint4* bw = (uint4*)&Bs[row*40 + ch];
        bw[0] = vv0;
        bw[1] = vv1;

        // prefetch next chunk (overlaps the MMA section below)
        if (jc + 1 < njc) {
            const __half* sp = sptr(jc + 1);
            sv0 = *(const uint4*)sp;  sv1 = *(const uint4*)(sp + 8);
            const __half* vp = vtp + (jc + 1)*32;
            vv0 = *(const uint4*)vp;  vv1 = *(const uint4*)(vp + 8);
        }
        __syncthreads();

        #pragma unroll
        for (int c = 0; c < 2; ++c) {
            uint32_t af[4][4], bf[4][2];
            #pragma unroll
            for (int mt = 0; mt < 4; ++mt)
                ldsm_x4(af[mt], aAddr + mt * 1280 + c * 32);
            #pragma unroll
            for (int nt = 0; nt < 4; ++nt)
                ldsm_x2(bf[nt], bAddr + nt * 640 + c * 32);
            #pragma unroll
            for (int mt = 0; mt < 4; ++mt)
                #pragma unroll
                for (int nt = 0; nt < 4; ++nt)
                    mma_f16(acc[mt][nt], af[mt], bf[nt]);
        }
        __syncthreads();
    }

    #pragma unroll
    for (int mt = 0; mt < 4; ++mt) {
        const int r0 = wm*64 + mt*16 + gid;
        #pragma unroll
        for (int nt = 0; nt < 4; ++nt) {
            const int cn = wn*32 + nt*8 + 2*tg;
            __half* C = ao + ((size_t)b*SEQ + i0)*DM + h*HD;
            *(uint32_t*)(C + (size_t)r0*DM + cn) =
                pack2(acc[mt][nt][0], acc[mt][nt][1]);
            *(uint32_t*)(C + (size_t)(r0+8)*DM + cn) =
                pack2(acc[mt][nt][2], acc[mt][nt][3]);
        }
    }
}

// ---------------- converts / transposes -------------------------------------
__global__ void k_cvt_x(const float* __restrict__ x, __half* __restrict__ xh, int n4)
{
    int i = blockIdx.x * blockDim.x + threadIdx.x;
    if (i >= n4) return;
    float4 v = ((const float4*)x)[i];
    ((uint2*)xh)[i] = make_uint2(pack2(v.x, v.y), pack2(v.z, v.w));
}

__global__ __launch_bounds__(256) void k_cvt_w(
    const float* __restrict__ src, __half* __restrict__ dst, int N, int K)
{
    __shared__ float tile[32][33];
    const int tx = threadIdx.x & 31, ty = threadIdx.x >> 5;
    const int r0 = blockIdx.y * 32, c0 = blockIdx.x * 32;
    #pragma unroll
    for (int i = 0; i < 32; i += 8)
        tile[ty + i][tx] = src[(size_t)(r0 + ty + i) * N + c0 + tx];
    __syncthreads();
    #pragma unroll
    for (int i = 0; i < 32; i += 8)
        dst[(size_t)(c0 + ty + i) * K + r0 + tx] = __float2half(tile[tx][ty + i]);
}

__global__ __launch_bounds__(256) void k_transpose_v(
    const __half* __restrict__ v, __half* __restrict__ vt)
{
    __shared__ __half tile[32][33];
    const int z = blockIdx.z, b = z >> 2, hk = z & 3;
    const int tx = threadIdx.x & 31, ty = threadIdx.x >> 5;
    const int r0 = blockIdx.y * 32, c0 = blockIdx.x * 32;
    #pragma unroll
    for (int i = 0; i < 32; i += 8)
        tile[ty + i][tx] = v[((size_t)b*SEQ + r0 + ty + i) * KVD + hk*HD + c0 + tx];
    __syncthreads();
    #pragma unroll
    for (int i = 0; i < 32; i += 8)
        vt[((size_t)(b*HKV + hk)*HD + c0 + ty + i) * SEQ + r0 + tx] = tile[tx][ty + i];
}

// ---------------- launch ------------------------------------------------------
extern "C" void kernel_launch(void* const* d_in, const int* in_sizes, int n_in,
                              void* d_out, int out_size)
{
    const float* x  = (const float*)d_in[0];
    const float* fc = (const float*)d_in[1];
    const float* fs = (const float*)d_in[2];
    const float* wq = (const float*)d_in[3];
    const float* bq = (const float*)d_in[4];
    const float* wk = (const float*)d_in[5];
    const float* bk = (const float*)d_in[6];
    const float* wv = (const float*)d_in[7];
    const float* bv = (const float*)d_in[8];
    const float* wo = (const float*)d_in[9];

    float* outp = (float*)d_out;
    float* attn = outp + (size_t)BSZ * SEQ * DM;

    __half *xh, *qh, *kh, *vh, *vt, *aoh, *wqt, *wkt, *wvt, *wot, *sh;
    float *pm, *pl, *Mv, *Li;
    cudaGetSymbolAddress((void**)&xh,  g_xh);
    cudaGetSymbolAddress((void**)&qh,  g_qh);
    cudaGetSymbolAddress((void**)&kh,  g_kh);
    cudaGetSymbolAddress((void**)&vh,  g_vh);
    cudaGetSymbolAddress((void**)&vt,  g_vt);
    cudaGetSymbolAddress((void**)&aoh, g_aoh);
    cudaGetSymbolAddress((void**)&wqt, g_wqt);
    cudaGetSymbolAddress((void**)&wkt, g_wkt);
    cudaGetSymbolAddress((void**)&wvt, g_wvt);
    cudaGetSymbolAddress((void**)&wot, g_wot);
    cudaGetSymbolAddress((void**)&sh,  g_sh);
    cudaGetSymbolAddress((void**)&pm,  g_pm);
    cudaGetSymbolAddress((void**)&pl,  g_pl);
    cudaGetSymbolAddress((void**)&Mv,  g_M);
    cudaGetSymbolAddress((void**)&Li,  g_Li);

    const float scale = 1.0f / sqrtf((float)DM);

    // conversions (launches 1-5)
    k_cvt_x<<<(MROWS*DM/4 + 255)/256, 256>>>(x, xh, MROWS*DM/4);
    k_cvt_w<<<dim3(DM/32,  DM/32), 256>>>(wq, wqt, DM,  DM);
    k_cvt_w<<<dim3(KVD/32, DM/32), 256>>>(wk, wkt, KVD, DM);
    k_cvt_w<<<dim3(KVD/32, DM/32), 256>>>(wv, wvt, KVD, DM);
    k_cvt_w<<<dim3(DM/32,  DM/32), 256>>>(wo, wot, DM,  DM);

    // launch 6 (ncu target): fused QKV projection + RoPE
    k_qkv<<<dim3(24, MROWS/128), 256>>>(xh, wqt, wkt, wvt, bq, bk, bv,
                                        qh, kh, vh, fc, fs);

    k_transpose_v<<<dim3(HD/32, SEQ/32, BSZ*HKV), 256>>>(vh, vt);

    // scores + upper-tile zero-fill fused
    k_scores2<<<dim3(NTILE, NTILE, NBH), 256>>>(qh, kh, sh, pm, pl, attn, scale);
    k_reduce<<<(NBH*SEQ + 255)/256, 256>>>(pm, pl, Mv, Li);
    k_pv<<<dim3(NTILE, NBH), 256>>>(sh, Mv, Li, vt, attn, aoh);

    k_proj_o<<<dim3(DM/128, MROWS/128), 256>>>(aoh, wot, outp);
}

// round 8
// speedup vs baseline: 5.4384x; 1.0668x over previous
#include <cuda_runtime.h>
#include <cuda_fp16.h>
#include <math.h>
#include <stdint.h>

#define BSZ 2
#define SEQ 2048
#define DM  2048
#define HQ  16
#define HKV 4
#define HD  128
#define MROWS (BSZ*SEQ)        // 4096
#define KVD (HKV*HD)           // 512
#define NBH (BSZ*HQ)           // 32
#define NTILE (SEQ/128)        // 16

// ---------------- persistent scratch ----------------------------------------
__device__ __half g_xh [(size_t)MROWS*DM];
__device__ __half g_qh [(size_t)MROWS*DM];
__device__ __half g_kh [(size_t)MROWS*KVD];
__device__ __half g_vh [(size_t)MROWS*KVD];
__device__ __half g_vt [(size_t)BSZ*HKV*HD*SEQ];   // [b][hk][d][s]
__device__ __half g_aoh[(size_t)MROWS*DM];
__device__ __half g_wqt[(size_t)DM*DM];            // [N][K]
__device__ __half g_wkt[(size_t)KVD*DM];
__device__ __half g_wvt[(size_t)KVD*DM];
__device__ __half g_wot[(size_t)DM*DM];
__device__ __half g_sh [(size_t)NBH*NTILE*NTILE*128*128];  // fp16 score tiles
__device__ float  g_pm [(size_t)NBH*SEQ*NTILE];    // per-tile row max
__device__ float  g_pl [(size_t)NBH*SEQ*NTILE];    // per-tile row expsum

// ---------------- helpers ---------------------------------------------------
__device__ __forceinline__ uint32_t pack2(float lo, float hi){
    __half2 h = __floats2half2_rn(lo, hi);
    return *reinterpret_cast<uint32_t*>(&h);
}
__device__ __forceinline__ uint32_t smem_u32(const void* p){
    uint32_t a;
    asm("{ .reg .u64 t; cvta.to.shared.u64 t, %1; cvt.u32.u64 %0, t; }"
        : "=r"(a) : "l"(p));
    return a;
}
__device__ __forceinline__ void cp16(uint32_t dst, const void* src){
    asm volatile("cp.async.cg.shared.global [%0], [%1], 16;"
        :: "r"(dst), "l"(src) : "memory");
}
#define CP_COMMIT() asm volatile("cp.async.commit_group;" ::: "memory")
#define CP_WAIT0()  asm volatile("cp.async.wait_group 0;" ::: "memory")
#define CP_WAIT1()  asm volatile("cp.async.wait_group 1;" ::: "memory")

__device__ __forceinline__ void ldsm_x4(uint32_t* r, uint32_t addr){
    asm volatile("ldmatrix.sync.aligned.m8n8.x4.shared.b16 {%0,%1,%2,%3}, [%4];"
        : "=r"(r[0]), "=r"(r[1]), "=r"(r[2]), "=r"(r[3]) : "r"(addr));
}
__device__ __forceinline__ void ldsm_x2(uint32_t* r, uint32_t addr){
    asm volatile("ldmatrix.sync.aligned.m8n8.x2.shared.b16 {%0,%1}, [%2];"
        : "=r"(r[0]), "=r"(r[1]) : "r"(addr));
}
__device__ __forceinline__ void mma_f16(float* d, const uint32_t* a, const uint32_t* b){
    asm volatile("mma.sync.aligned.m16n8k16.row.col.f32.f16.f16.f32 "
        "{%0,%1,%2,%3}, {%4,%5,%6,%7}, {%8,%9}, {%0,%1,%2,%3};"
        : "+f"(d[0]), "+f"(d[1]), "+f"(d[2]), "+f"(d[3])
        : "r"(a[0]), "r"(a[1]), "r"(a[2]), "r"(a[3]), "r"(b[0]), "r"(b[1]));
}

#define ACC_INIT(acc) \
    _Pragma("unroll") for (int i=0;i<4;i++) \
        _Pragma("unroll") for (int j=0;j<4;j++) \
            _Pragma("unroll") for (int v=0;v<4;v++) acc[i][j][v]=0.f;

#define PROJ_SMEM (6 * 5120 * 2)   // 3 stages x (A,B) x 5120 halves = 61440 B

// ============ fp16 proj core: 128x128 tile, 3-stage cp.async pipeline =======
// 8 warps (2m x 4n), warp 64x32, kTile 32, wait_group 1 keeps 1 group in flight
template<int CF>
__device__ __forceinline__ void tc_fp16(
    const __half* __restrict__ A, int lda, const __half* __restrict__ B, int ldb,
    void* Cv, int ldc, const float* __restrict__ bias, float scale, int niter,
    const float* __restrict__ cosb, const float* __restrict__ sinb, int srow)
{
    extern __shared__ __half dsm[];
    __half* Asb = dsm;             // 3 stages x 5120
    __half* Bsb = dsm + 3*5120;

    const int t = threadIdx.x, lane = t & 31, w = t >> 5;
    const int wm = w >> 2, wn = w & 3, gid = lane >> 2, tg = lane & 3;
    const int row = t >> 1, ch = (t & 1) * 16;

    float acc[4][4][4];
    ACC_INIT(acc)

    const __half* Ag = A + (size_t)row * lda + ch;
    const __half* Bg = B + (size_t)row * ldb + ch;

    const uint32_t aoff = ((wm*64 + (lane & 15)) * 40 + ((lane >> 4) << 3)) << 1;
    const uint32_t boff = ((wn*32 + (lane & 7)) * 40 + (((lane >> 3) & 1) << 3)) << 1;
    const uint32_t soff = (row*40 + ch) << 1;

    // rotating per-stage addresses (registers, no dynamic indexing)
    uint32_t stA0 = smem_u32(Asb) + soff,          stB0 = smem_u32(Bsb) + soff;
    uint32_t stA1 = stA0 + 10240,                  stB1 = stB0 + 10240;
    uint32_t stA2 = stA1 + 10240,                  stB2 = stB1 + 10240;
    uint32_t ldA0 = smem_u32(Asb) + aoff,          ldB0 = smem_u32(Bsb) + boff;
    uint32_t ldA1 = ldA0 + 10240,                  ldB1 = ldB0 + 10240;
    uint32_t ldA2 = ldA1 + 10240,                  ldB2 = ldB1 + 10240;

    // prologue: iters 0,1 into stages 0,1
    cp16(stA0, Ag);      cp16(stA0 + 16, Ag + 8);
    cp16(stB0, Bg);      cp16(stB0 + 16, Bg + 8);
    CP_COMMIT();
    cp16(stA1, Ag + 32); cp16(stA1 + 16, Ag + 40);
    cp16(stB1, Bg + 32); cp16(stB1 + 16, Bg + 40);
    CP_COMMIT();

    for (int it = 0; it < niter; ++it) {
        if (it + 1 < niter) { CP_WAIT1(); } else { CP_WAIT0(); }
        __syncthreads();
        if (it + 2 < niter) {
            const __half* a = Ag + (size_t)(it + 2) * 32;
            const __half* b = Bg + (size_t)(it + 2) * 32;
            cp16(stA2, a); cp16(stA2 + 16, a + 8);
            cp16(stB2, b); cp16(stB2 + 16, b + 8);
            CP_COMMIT();
        }
        #pragma unroll
        for (int c = 0; c < 2; ++c) {
            uint32_t af[4][4], bf[4][2];
            #pragma unroll
            for (int mt = 0; mt < 4; ++mt)
                ldsm_x4(af[mt], ldA0 + mt * 1280 + c * 32);
            #pragma unroll
            for (int nt = 0; nt < 4; ++nt)
                ldsm_x2(bf[nt], ldB0 + nt * 640 + c * 32);
            #pragma unroll
            for (int mt = 0; mt < 4; ++mt)
                #pragma unroll
                for (int nt = 0; nt < 4; ++nt)
                    mma_f16(acc[mt][nt], af[mt], bf[nt]);
        }
        // rotate stages
        uint32_t tmp;
        tmp = stA0; stA0 = stA1; stA1 = stA2; stA2 = tmp;
        tmp = stB0; stB0 = stB1; stB1 = stB2; stB2 = tmp;
        tmp = ldA0; ldA0 = ldA1; ldA1 = ldA2; ldA2 = tmp;
        tmp = ldB0; ldB0 = ldB1; ldB1 = ldB2; ldB2 = tmp;
    }

    #pragma unroll
    for (int mt = 0; mt < 4; ++mt) {
        const int r0 = wm*64 + mt*16 + gid;
        #pragma unroll
        for (int nt = 0; nt < 4; ++nt) {
            const int cn = wn*32 + nt*8 + 2*tg;
            float b0 = 0.f, b1 = 0.f;
            if (bias) { b0 = bias[cn]; b1 = bias[cn+1]; }
            float v00 = acc[mt][nt][0]*scale + b0;
            float v01 = acc[mt][nt][1]*scale + b1;
            float v10 = acc[mt][nt][2]*scale + b0;
            float v11 = acc[mt][nt][3]*scale + b1;
            if (cosb) {
                const int p = cn >> 1;
                const float c0 = cosb[(srow + r0) * 64 + p];
                const float s0 = sinb[(srow + r0) * 64 + p];
                const float c1 = cosb[(srow + r0 + 8) * 64 + p];
                const float s1 = sinb[(srow + r0 + 8) * 64 + p];
                float t0 = v00*c0 - v01*s0, t1 = v00*s0 + v01*c0;
                v00 = t0; v01 = t1;
                t0 = v10*c1 - v11*s1; t1 = v10*s1 + v11*c1;
                v10 = t0; v11 = t1;
            }
            if (CF == 1) {
                float* C = (float*)Cv;
                *(float2*)(C + (size_t)r0*ldc + cn)     = make_float2(v00, v01);
                *(float2*)(C + (size_t)(r0+8)*ldc + cn) = make_float2(v10, v11);
            } else {
                __half* C = (__half*)Cv;
                *(uint32_t*)(C + (size_t)r0*ldc + cn)     = pack2(v00, v01);
                *(uint32_t*)(C + (size_t)(r0+8)*ldc + cn) = pack2(v10, v11);
            }
        }
    }
}

// ---------------- GEMM wrappers ---------------------------------------------
__global__ __launch_bounds__(256, 2) void k_qkv(
    const __half* __restrict__ xh,
    const __half* __restrict__ wqt, const __half* __restrict__ wkt,
    const __half* __restrict__ wvt,
    const float* __restrict__ bq, const float* __restrict__ bk,
    const float* __restrict__ bv,
    __half* __restrict__ qh, __half* __restrict__ kh, __half* __restrict__ vh,
    const float* __restrict__ cosb, const float* __restrict__ sinb)
{
    const int bx = blockIdx.x, by = blockIdx.y;
    const __half* A = xh + (size_t)by * 128 * DM;
    const int srow = (by & 15) * 128;
    if (bx < 16) {
        tc_fp16<0>(A, DM, wqt + (size_t)bx*128*DM, DM,
                   qh + (size_t)by*128*DM + bx*128, DM,
                   bq + bx*128, 1.0f, DM/32, cosb, sinb, srow);
    } else if (bx < 20) {
        const int c = bx - 16;
        tc_fp16<0>(A, DM, wkt + (size_t)c*128*DM, DM,
                   kh + (size_t)by*128*KVD + c*128, KVD,
                   bk + c*128, 1.0f, DM/32, cosb, sinb, srow);
    } else {
        const int c = bx - 20;
        tc_fp16<0>(A, DM, wvt + (size_t)c*128*DM, DM,
                   vh + (size_t)by*128*KVD + c*128, KVD,
                   bv + c*128, 1.0f, DM/32, (const float*)0, (const float*)0, 0);
    }
}

__global__ __launch_bounds__(256, 2) void k_proj_o(
    const __half* __restrict__ X, const __half* __restrict__ Wt,
    float* __restrict__ C)
{
    tc_fp16<1>(X + (size_t)blockIdx.y*128*DM, DM,
               Wt + (size_t)blockIdx.x*128*DM, DM,
               C + (size_t)blockIdx.y*128*DM + blockIdx.x*128, DM,
               (const float*)0, 1.0f, DM/32, (const float*)0, (const float*)0, 0);
}

// ======== scores: S tile fp16 + partials; upper tiles zero-fill attn ========
__global__ __launch_bounds__(256) void k_scores2(
    const __half* __restrict__ q, const __half* __restrict__ k,
    __half* __restrict__ sh, float* __restrict__ pm, float* __restrict__ pl,
    float* __restrict__ attn, float scale)
{
    const int bx = blockIdx.x, by = blockIdx.y;
    const int bh = blockIdx.z, b = bh >> 4, h = bh & 15, hk = h >> 2;

    if (bx > by) {   // strictly-upper tile: zero-fill the attn output here
        float* base = attn + ((size_t)bh*SEQ + by*128)*SEQ + bx*128;
        const float4 z = make_float4(0.f, 0.f, 0.f, 0.f);
        for (int f = threadIdx.x; f < 128*32; f += 256) {
            const int r = f >> 5, c4 = f & 31;
            *(float4*)(base + (size_t)r*SEQ + c4*4) = z;
        }
        return;
    }

    __shared__ __half As[2][128*40];
    __shared__ __half Bs[2][128*40];
    __shared__ float sm_m[4][128];
    __shared__ float sm_l[4][128];
    const int t = threadIdx.x, lane = t & 31, w = t >> 5;
    const int wm = w >> 2, wn = w & 3, gid = lane >> 2, tg = lane & 3;
    const int row = t >> 1, ch = (t & 1) * 16;

    float acc[4][4][4];
    ACC_INIT(acc)

    const __half* Ag = q + ((size_t)b*SEQ + by*128 + row) * DM  + h*HD  + ch;
    const __half* Bg = k + ((size_t)b*SEQ + bx*128 + row) * KVD + hk*HD + ch;
    uint32_t sa[2], sb[2];
    sa[0] = smem_u32(&As[0][row*40 + ch]);
    sa[1] = smem_u32(&As[1][row*40 + ch]);
    sb[0] = smem_u32(&Bs[0][row*40 + ch]);
    sb[1] = smem_u32(&Bs[1][row*40 + ch]);
    uint32_t aAddr[2], bAddr[2];
    #pragma unroll
    for (int s = 0; s < 2; ++s) {
        aAddr[s] = smem_u32(&As[s][0]) +
            (((wm*64 + (lane & 15)) * 40 + ((lane >> 4) << 3)) << 1);
        bAddr[s] = smem_u32(&Bs[s][0]) +
            (((wn*32 + (lane & 7)) * 40 + (((lane >> 3) & 1) << 3)) << 1);
    }

    cp16(sa[0], Ag);      cp16(sa[0] + 16, Ag + 8);
    cp16(sb[0], Bg);      cp16(sb[0] + 16, Bg + 8);
    CP_COMMIT();

    for (int it = 0; it < HD/32; ++it) {
        const int cur = it & 1;
        CP_WAIT0();
        __syncthreads();
        if (it + 1 < HD/32) {
            const int nxt = cur ^ 1;
            const __half* a = Ag + (size_t)(it + 1) * 32;
            const __half* b2 = Bg + (size_t)(it + 1) * 32;
            cp16(sa[nxt], a);  cp16(sa[nxt] + 16, a + 8);
            cp16(sb[nxt], b2); cp16(sb[nxt] + 16, b2 + 8);
            CP_COMMIT();
        }
        #pragma unroll
        for (int c = 0; c < 2; ++c) {
            uint32_t af[4][4], bf[4][2];
            #pragma unroll
            for (int mt = 0; mt < 4; ++mt)
                ldsm_x4(af[mt], aAddr[cur] + mt * 1280 + c * 32);
            #pragma unroll
            for (int nt = 0; nt < 4; ++nt)
                ldsm_x2(bf[nt], bAddr[cur] + nt * 640 + c * 32);
            #pragma unroll
            for (int mt = 0; mt < 4; ++mt)
                #pragma unroll
                for (int nt = 0; nt < 4; ++nt)
                    mma_f16(acc[mt][nt], af[mt], bf[nt]);
        }
    }

    const bool diag = (bx == by);
    __half* tile = sh + (((size_t)bh*NTILE + by)*NTILE + bx) * (128*128);

    #pragma unroll
    for (int mt = 0; mt < 4; ++mt) {
        #pragma unroll
        for (int hv = 0; hv < 2; ++hv) {
            const int r = wm*64 + mt*16 + gid + hv*8;
            float vals[8];
            #pragma unroll
            for (int nt = 0; nt < 4; ++nt) {
                vals[nt*2]   = acc[mt][nt][hv*2]   * scale;
                vals[nt*2+1] = acc[mt][nt][hv*2+1] * scale;
                const int cn = wn*32 + nt*8 + 2*tg;
                *(uint32_t*)(tile + (size_t)r*128 + cn) =
                    pack2(vals[nt*2], vals[nt*2+1]);
            }
            if (diag) {
                #pragma unroll
                for (int nt = 0; nt < 4; ++nt) {
                    const int cn = wn*32 + nt*8 + 2*tg;
                    if (cn     > r) vals[nt*2]   = -1e30f;
                    if (cn + 1 > r) vals[nt*2+1] = -1e30f;
                }
            }
            float m = -1e30f;
            #pragma unroll
            for (int i = 0; i < 8; ++i) m = fmaxf(m, vals[i]);
            m = fmaxf(m, __shfl_xor_sync(0xFFFFFFFFu, m, 1));
            m = fmaxf(m, __shfl_xor_sync(0xFFFFFFFFu, m, 2));
            float l = 0.f;
            #pragma unroll
            for (int i = 0; i < 8; ++i)
                if (vals[i] > -1e29f) l += __expf(vals[i] - m);
            l += __shfl_xor_sync(0xFFFFFFFFu, l, 1);
            l += __shfl_xor_sync(0xFFFFFFFFu, l, 2);
            if (tg == 0) { sm_m[wn][r] = m; sm_l[wn][r] = l; }
        }
    }
    __syncthreads();
    if (t < 128) {
        float M = -1e30f;
        #pragma unroll
        for (int w2 = 0; w2 < 4; ++w2) M = fmaxf(M, sm_m[w2][t]);
        float L = 0.f;
        #pragma unroll
        for (int w2 = 0; w2 < 4; ++w2)
            if (sm_m[w2][t] > -1e29f) L += sm_l[w2][t] * __expf(sm_m[w2][t] - M);
        const size_t ridx = ((size_t)bh*SEQ + by*128 + t) * NTILE + bx;
        pm[ridx] = M; pl[ridx] = L;
    }
}

// ======== fused reduce + normalize + P write + P@V ==========================
__global__ __launch_bounds__(256) void k_pv(
    const __half* __restrict__ sh, const float* __restrict__ pm,
    const float* __restrict__ pl, const __half* __restrict__ vt,
    float* __restrict__ attn, __half* __restrict__ ao)
{
    const int by = NTILE - 1 - blockIdx.x;       // big tiles first
    const int bh = blockIdx.y;
    const int b = bh >> 4, h = bh & 15, hk = h >> 2;
    const int i0 = by * 128;

    __shared__ __half As[128*40];
    __shared__ __half Bs[128*40];
    __shared__ float sM[128], sL[128];
    const int t = threadIdx.x, lane = t & 31, w = t >> 5;
    const int wm = w >> 2, wn = w & 3, gid = lane >> 2, tg = lane & 3;
    const int row = t >> 1, ch = (t & 1) * 16;

    // in-kernel row reduction (nt = by+1 uniform across the tile)
    if (t < 128) {
        const float* pmr = pm + ((size_t)bh*SEQ + i0 + t) * NTILE;
        const float* plr = pl + ((size_t)bh*SEQ + i0 + t) * NTILE;
        float M = -1e30f;
        for (int t2 = 0; t2 <= by; ++t2) M = fmaxf(M, pmr[t2]);
        float L = 0.f;
        for (int t2 = 0; t2 <= by; ++t2)
            if (pmr[t2] > -1e29f) L += plr[t2] * __expf(pmr[t2] - M);
        sM[t] = M; sL[t] = 1.0f / L;
    }

    float acc[4][4][4];
    ACC_INIT(acc)

    const __half* shb = sh + ((size_t)bh*NTILE + by)*NTILE*(128*128);
    const __half* vtp = vt + (size_t)(b*HKV + hk)*HD*SEQ + (size_t)row*SEQ + ch;
    float* arow = attn + ((size_t)bh*SEQ + i0 + row)*SEQ;

    const uint32_t aAddr = smem_u32(As) +
        (((wm*64 + (lane & 15)) * 40 + ((lane >> 4) << 3)) << 1);
    const uint32_t bAddr = smem_u32(Bs) +
        (((wn*32 + (lane & 7)) * 40 + (((lane >> 3) & 1) << 3)) << 1);

    const int njc = (by + 1) * 4;                  // 32-wide j chunks

    auto sptr = [&](int jc) -> const __half* {
        const int tj = jc >> 2, jin = (jc & 3) * 32;
        return shb + (size_t)tj*(128*128) + (size_t)row*128 + jin + ch;
    };

    uint4 sv0, sv1, vv0, vv1;
    {
        const __half* sp = sptr(0);
        sv0 = *(const uint4*)sp;  sv1 = *(const uint4*)(sp + 8);
        vv0 = *(const uint4*)vtp; vv1 = *(const uint4*)(vtp + 8);
    }
    __syncthreads();                               // sM/sL ready
    const float Mrow = sM[row], invL = sL[row];

    for (int jc = 0; jc < njc; ++jc) {
        const int tj = jc >> 2, jin = (jc & 3) * 32;

        float p[16];
        {
            const __half2* h2 = (const __half2*)&sv0;
            #pragma unroll
            for (int g = 0; g < 4; ++g) {
                float2 f = __half22float2(h2[g]);
                p[g*2]   = __expf(f.x - Mrow) * invL;
                p[g*2+1] = __expf(f.y - Mrow) * invL;
            }
            const __half2* h3 = (const __half2*)&sv1;
            #pragma unroll
            for (int g = 0; g < 4; ++g) {
                float2 f = __half22float2(h3[g]);
                p[8+g*2]   = __expf(f.x - Mrow) * invL;
                p[8+g*2+1] = __expf(f.y - Mrow) * invL;
            }
        }
        if (tj == by) {
            #pragma unroll
            for (int kk = 0; kk < 16; ++kk)
                if (jin + ch + kk > row) p[kk] = 0.f;
        }
        float* ap = arow + tj*128 + jin + ch;
        *(float4*)(ap)      = make_float4(p[0],  p[1],  p[2],  p[3]);
        *(float4*)(ap + 4)  = make_float4(p[4],  p[5],  p[6],  p[7]);
        *(float4*)(ap + 8)  = make_float4(p[8],  p[9],  p[10], p[11]);
        *(float4*)(ap + 12) = make_float4(p[12], p[13], p[14], p[15]);

        uint4* aw = (uint4*)&As[row*40 + ch];
        aw[0] = make_uint4(pack2(p[0],p[1]),  pack2(p[2],p[3]),
                           pack2(p[4],p[5]),  pack2(p[6],p[7]));
        aw[1] = make_uint4(pack2(p[8],p[9]),  pack2(p[10],p[11]),
                           pack2(p[12],p[13]),pack2(p[14],p[15]));
        uint4* bw = (uint4*)&Bs[row*40 + ch];
        bw[0] = vv0;
        bw[1] = vv1;

        if (jc + 1 < njc) {
            const __half* sp = sptr(jc + 1);
            sv0 = *(const uint4*)sp;  sv1 = *(const uint4*)(sp + 8);
            const __half* vp = vtp + (jc + 1)*32;
            vv0 = *(const uint4*)vp;  vv1 = *(const uint4*)(vp + 8);
        }
        __syncthreads();

        #pragma unroll
        for (int c = 0; c < 2; ++c) {
            uint32_t af[4][4], bf[4][2];
            #pragma unroll
            for (int mt = 0; mt < 4; ++mt)
                ldsm_x4(af[mt], aAddr + mt * 1280 + c * 32);
            #pragma unroll
            for (int nt = 0; nt < 4; ++nt)
                ldsm_x2(bf[nt], bAddr + nt * 640 + c * 32);
            #pragma unroll
            for (int mt = 0; mt < 4; ++mt)
                #pragma unroll
                for (int nt = 0; nt < 4; ++nt)
                    mma_f16(acc[mt][nt], af[mt], bf[nt]);
        }
        __syncthreads();
    }

    #pragma unroll
    for (int mt = 0; mt < 4; ++mt) {
        const int r0 = wm*64 + mt*16 + gid;
        #pragma unroll
        for (int nt = 0; nt < 4; ++nt) {
            const int cn = wn*32 + nt*8 + 2*tg;
            __half* C = ao + ((size_t)b*SEQ + i0)*DM + h*HD;
            *(uint32_t*)(C + (size_t)r0*DM + cn) =
                pack2(acc[mt][nt][0], acc[mt][nt][1]);
            *(uint32_t*)(C + (size_t)(r0+8)*DM + cn) =
                pack2(acc[mt][nt][2], acc[mt][nt][3]);
        }
    }
}

// ---------------- converts / transposes -------------------------------------
__global__ void k_cvt_x(const float* __restrict__ x, __half* __restrict__ xh, int n4)
{
    int i = blockIdx.x * blockDim.x + threadIdx.x;
    if (i >= n4) return;
    float4 v = ((const float4*)x)[i];
    ((uint2*)xh)[i] = make_uint2(pack2(v.x, v.y), pack2(v.z, v.w));
}

__global__ __launch_bounds__(256) void k_cvt_w(
    const float* __restrict__ src, __half* __restrict__ dst, int N, int K)
{
    __shared__ float tile[32][33];
    const int tx = threadIdx.x & 31, ty = threadIdx.x >> 5;
    const int r0 = blockIdx.y * 32, c0 = blockIdx.x * 32;
    #pragma unroll
    for (int i = 0; i < 32; i += 8)
        tile[ty + i][tx] = src[(size_t)(r0 + ty + i) * N + c0 + tx];
    __syncthreads();
    #pragma unroll
    for (int i = 0; i < 32; i += 8)
        dst[(size_t)(c0 + ty + i) * K + r0 + tx] = __float2half(tile[tx][ty + i]);
}

__global__ __launch_bounds__(256) void k_transpose_v(
    const __half* __restrict__ v, __half* __restrict__ vt)
{
    __shared__ __half tile[32][33];
    const int z = blockIdx.z, b = z >> 2, hk = z & 3;
    const int tx = threadIdx.x & 31, ty = threadIdx.x >> 5;
    const int r0 = blockIdx.y * 32, c0 = blockIdx.x * 32;
    #pragma unroll
    for (int i = 0; i < 32; i += 8)
        tile[ty + i][tx] = v[((size_t)b*SEQ + r0 + ty + i) * KVD + hk*HD + c0 + tx];
    __syncthreads();
    #pragma unroll
    for (int i = 0; i < 32; i += 8)
        vt[((size_t)(b*HKV + hk)*HD + c0 + ty + i) * SEQ + r0 + tx] = tile[tx][ty + i];
}

// ---------------- launch ------------------------------------------------------
extern "C" void kernel_launch(void* const* d_in, const int* in_sizes, int n_in,
                              void* d_out, int out_size)
{
    const float* x  = (const float*)d_in[0];
    const float* fc = (const float*)d_in[1];
    const float* fs = (const float*)d_in[2];
    const float* wq = (const float*)d_in[3];
    const float* bq = (const float*)d_in[4];
    const float* wk = (const float*)d_in[5];
    const float* bk = (const float*)d_in[6];
    const float* wv = (const float*)d_in[7];
    const float* bv = (const float*)d_in[8];
    const float* wo = (const float*)d_in[9];

    float* outp = (float*)d_out;
    float* attn = outp + (size_t)BSZ * SEQ * DM;

    __half *xh, *qh, *kh, *vh, *vt, *aoh, *wqt, *wkt, *wvt, *wot, *sh;
    float *pm, *pl;
    cudaGetSymbolAddress((void**)&xh,  g_xh);
    cudaGetSymbolAddress((void**)&qh,  g_qh);
    cudaGetSymbolAddress((void**)&kh,  g_kh);
    cudaGetSymbolAddress((void**)&vh,  g_vh);
    cudaGetSymbolAddress((void**)&vt,  g_vt);
    cudaGetSymbolAddress((void**)&aoh, g_aoh);
    cudaGetSymbolAddress((void**)&wqt, g_wqt);
    cudaGetSymbolAddress((void**)&wkt, g_wkt);
    cudaGetSymbolAddress((void**)&wvt, g_wvt);
    cudaGetSymbolAddress((void**)&wot, g_wot);
    cudaGetSymbolAddress((void**)&sh,  g_sh);
    cudaGetSymbolAddress((void**)&pm,  g_pm);
    cudaGetSymbolAddress((void**)&pl,  g_pl);

    cudaFuncSetAttribute(k_qkv,   cudaFuncAttributeMaxDynamicSharedMemorySize, PROJ_SMEM);
    cudaFuncSetAttribute(k_proj_o,cudaFuncAttributeMaxDynamicSharedMemorySize, PROJ_SMEM);

    const float scale = 1.0f / sqrtf((float)DM);

    // conversions (launches 1-5)
    k_cvt_x<<<(MROWS*DM/4 + 255)/256, 256>>>(x, xh, MROWS*DM/4);
    k_cvt_w<<<dim3(DM/32,  DM/32), 256>>>(wq, wqt, DM,  DM);
    k_cvt_w<<<dim3(KVD/32, DM/32), 256>>>(wk, wkt, KVD, DM);
    k_cvt_w<<<dim3(KVD/32, DM/32), 256>>>(wv, wvt, KVD, DM);
    k_cvt_w<<<dim3(DM/32,  DM/32), 256>>>(wo, wot, DM,  DM);

    // launch 6 (ncu target): fused QKV projection + RoPE
    k_qkv<<<dim3(24, MROWS/128), 256, PROJ_SMEM>>>(xh, wqt, wkt, wvt, bq, bk, bv,
                                                   qh, kh, vh, fc, fs);

    k_transpose_v<<<dim3(HD/32, SEQ/32, BSZ*HKV), 256>>>(vh, vt);

    k_scores2<<<dim3(NTILE, NTILE, NBH), 256>>>(qh, kh, sh, pm, pl, attn, scale);
    k_pv<<<dim3(NTILE, NBH), 256>>>(sh, pm, pl, vt, attn, aoh);

    k_proj_o<<<dim3(DM/128, MROWS/128), 256, PROJ_SMEM>>>(aoh, wot, outp);
}